// round 1
// baseline (speedup 1.0000x reference)
#include <cuda_runtime.h>

// ---------------------------------------------------------------------------
// DeformAttn layer: fp32 baseline
//   1. value = src @ W_val + b_val
//   2. off   = query @ W_off + b_off      (N=64)
//      aw    = query @ W_aw  + b_aw       (N=32)
//   3. bilinear sample + softmax(aw) einsum -> attn
//   4. tmp = attn @ W_out + b_out ; q2 = LN(query + tmp)
//   5. ffn = relu(q2 @ W1 + b1) @ W2 + b2 ; out = LN(q2 + ffn)
// ---------------------------------------------------------------------------

#define DEV_INLINE __device__ __forceinline__

constexpr int BB   = 8;
constexpr int LQ   = 10000;
constexpr int CDIM = 256;
constexpr int NHD  = 8;     // heads
constexpr int NPT  = 4;     // points
constexpr int DFF  = 1024;
constexpr int HIMG = 100;
constexpr int WIMG = 100;
constexpr int HD   = 32;    // head dim
constexpr int MTOK = BB * LQ;  // 80000

// Scratch (static device arrays; no allocation in kernel_launch)
__device__ float g_value[MTOK * CDIM];
__device__ float g_off  [MTOK * NHD * NPT * 2];
__device__ float g_aw   [MTOK * NHD * NPT];
__device__ float g_attn [MTOK * CDIM];
__device__ float g_tmp  [MTOK * CDIM];
__device__ float g_q2   [MTOK * CDIM];
__device__ float g_ffn  [MTOK * DFF];

// ---------------------------------------------------------------------------
// GEMM: C[M,N] = A[M,K] @ B[K,N] + bias, optional relu.
// M is always a multiple of 128 (80000). N may be < BN (guarded). K % 16 == 0.
// ---------------------------------------------------------------------------
constexpr int BM = 128, BN = 128, BK = 16, TM = 8, TN = 8;

__global__ __launch_bounds__(256) void gemm_kernel(
    const float* __restrict__ A, const float* __restrict__ Bmat,
    const float* __restrict__ bias, float* __restrict__ C,
    int N, int K, int relu)
{
    __shared__ float As[BK][BM];  // transposed A tile
    __shared__ float Bs[BK][BN];

    const int tid  = threadIdx.x;
    const int tcol = tid & 15;   // 0..15
    const int trow = tid >> 4;   // 0..15
    const size_t mbase = (size_t)blockIdx.y * BM;
    const int    nbase = blockIdx.x * BN;

    float acc[TM][TN];
#pragma unroll
    for (int m = 0; m < TM; ++m)
#pragma unroll
        for (int n = 0; n < TN; ++n) acc[m][n] = 0.f;

    const int aRow = tid >> 2;        // 0..63 (two passes -> 128 rows)
    const int aCol = (tid & 3) << 2;  // 0,4,8,12
    const int bRow = tid >> 5;        // 0..7  (two passes -> 16 rows)
    const int bCol = (tid & 31) << 2; // 0..124

    const float* Ab = A + mbase * (size_t)K;

    for (int k0 = 0; k0 < K; k0 += BK) {
        // load A tile (transposed into As)
#pragma unroll
        for (int i = 0; i < 2; ++i) {
            int r = aRow + i * 64;
            float4 v = *(const float4*)(Ab + (size_t)r * K + k0 + aCol);
            As[aCol + 0][r] = v.x;
            As[aCol + 1][r] = v.y;
            As[aCol + 2][r] = v.z;
            As[aCol + 3][r] = v.w;
        }
        // load B tile (N-guarded)
#pragma unroll
        for (int i = 0; i < 2; ++i) {
            int r   = bRow + i * 8;
            int col = nbase + bCol;
            float4 v;
            if (col + 3 < N) {
                v = *(const float4*)(Bmat + (size_t)(k0 + r) * N + col);
            } else {
                v.x = (col + 0 < N) ? Bmat[(size_t)(k0 + r) * N + col + 0] : 0.f;
                v.y = (col + 1 < N) ? Bmat[(size_t)(k0 + r) * N + col + 1] : 0.f;
                v.z = (col + 2 < N) ? Bmat[(size_t)(k0 + r) * N + col + 2] : 0.f;
                v.w = (col + 3 < N) ? Bmat[(size_t)(k0 + r) * N + col + 3] : 0.f;
            }
            *(float4*)&Bs[r][bCol] = v;
        }
        __syncthreads();

#pragma unroll
        for (int kk = 0; kk < BK; ++kk) {
            float ra[TM], rb[TN];
            *(float4*)&ra[0] = *(const float4*)&As[kk][trow * TM];
            *(float4*)&ra[4] = *(const float4*)&As[kk][trow * TM + 4];
            *(float4*)&rb[0] = *(const float4*)&Bs[kk][tcol * TN];
            *(float4*)&rb[4] = *(const float4*)&Bs[kk][tcol * TN + 4];
#pragma unroll
            for (int m = 0; m < TM; ++m)
#pragma unroll
                for (int n = 0; n < TN; ++n)
                    acc[m][n] = fmaf(ra[m], rb[n], acc[m][n]);
        }
        __syncthreads();
    }

    // epilogue: bias (+relu), N-guarded store
#pragma unroll
    for (int m = 0; m < TM; ++m) {
        size_t row = mbase + trow * TM + m;
#pragma unroll
        for (int n = 0; n < TN; ++n) {
            int col = nbase + tcol * TN + n;
            if (col < N) {
                float v = acc[m][n] + bias[col];
                if (relu) v = fmaxf(v, 0.f);
                C[row * (size_t)N + col] = v;
            }
        }
    }
}

// ---------------------------------------------------------------------------
// Bilinear sampling + softmax(aw) + einsum -> attn[token, h*32+d]
// One block per token; thread t -> (h = t/32, d = t%32).
// ---------------------------------------------------------------------------
DEV_INLINE float corner_val(const float* __restrict__ vb, int x, int y, float w)
{
    if (x < 0 || x >= WIMG || y < 0 || y >= HIMG) return 0.f;
    return vb[(size_t)(y * WIMG + x) * CDIM] * w;
}

__global__ __launch_bounds__(256) void sample_kernel(
    const float* __restrict__ refp, float* __restrict__ attn)
{
    __shared__ float s_loc[NHD * NPT * 2];
    __shared__ float s_aw[NHD * NPT];

    const int token = blockIdx.x;
    const int b     = token / LQ;
    const int tid   = threadIdx.x;

    if (tid < 32) {  // full warp 0; idx = h*4 + p
        const int idx = tid;
        float ox = g_off[(size_t)token * 64 + idx * 2 + 0];
        float oy = g_off[(size_t)token * 64 + idx * 2 + 1];
        float rx = refp[(size_t)token * 2 + 0];
        float ry = refp[(size_t)token * 2 + 1];
        s_loc[idx * 2 + 0] = rx + ox * (1.0f / WIMG);
        s_loc[idx * 2 + 1] = ry + oy * (1.0f / HIMG);

        float logit = g_aw[(size_t)token * 32 + idx];
        float mx = logit;
        mx = fmaxf(mx, __shfl_xor_sync(0xffffffffu, mx, 1));
        mx = fmaxf(mx, __shfl_xor_sync(0xffffffffu, mx, 2));
        float e = __expf(logit - mx);
        float s = e;
        s += __shfl_xor_sync(0xffffffffu, s, 1);
        s += __shfl_xor_sync(0xffffffffu, s, 2);
        s_aw[idx] = e / s;
    }
    __syncthreads();

    const int h = tid >> 5;
    const int d = tid & 31;
    const float* vb = g_value + (size_t)b * LQ * CDIM + h * HD + d;

    float acc = 0.f;
#pragma unroll
    for (int p = 0; p < NPT; ++p) {
        float x = s_loc[(h * NPT + p) * 2 + 0] * WIMG - 0.5f;
        float y = s_loc[(h * NPT + p) * 2 + 1] * HIMG - 0.5f;
        float x0f = floorf(x), y0f = floorf(y);
        float fx = x - x0f, fy = y - y0f;
        int x0 = (int)x0f, y0 = (int)y0f;
        float a = s_aw[h * NPT + p];
        float w00 = a * (1.f - fx) * (1.f - fy);
        float w10 = a * fx * (1.f - fy);
        float w01 = a * (1.f - fx) * fy;
        float w11 = a * fx * fy;
        acc += corner_val(vb, x0,     y0,     w00);
        acc += corner_val(vb, x0 + 1, y0,     w10);
        acc += corner_val(vb, x0,     y0 + 1, w01);
        acc += corner_val(vb, x0 + 1, y0 + 1, w11);
    }
    attn[(size_t)token * CDIM + h * HD + d] = acc;
}

// ---------------------------------------------------------------------------
// Fused residual + LayerNorm: out = LN(x + y) * g + be. One block per row.
// ---------------------------------------------------------------------------
__global__ __launch_bounds__(256) void add_ln_kernel(
    const float* __restrict__ x, const float* __restrict__ y,
    const float* __restrict__ g, const float* __restrict__ be,
    float* __restrict__ out)
{
    const int row = blockIdx.x;
    const int t   = threadIdx.x;
    __shared__ float red[8];
    __shared__ float stat[2];

    size_t i = (size_t)row * CDIM + t;
    float v = x[i] + y[i];

    // mean
    float s = v;
#pragma unroll
    for (int o = 16; o; o >>= 1) s += __shfl_xor_sync(0xffffffffu, s, o);
    if ((t & 31) == 0) red[t >> 5] = s;
    __syncthreads();
    if (t < 8) {
        float r = red[t];
#pragma unroll
        for (int o = 4; o; o >>= 1) r += __shfl_xor_sync(0x000000ffu, r, o);
        if (t == 0) stat[0] = r * (1.0f / CDIM);
    }
    __syncthreads();
    float m   = stat[0];
    float dlt = v - m;

    // variance
    float s2 = dlt * dlt;
#pragma unroll
    for (int o = 16; o; o >>= 1) s2 += __shfl_xor_sync(0xffffffffu, s2, o);
    if ((t & 31) == 0) red[t >> 5] = s2;
    __syncthreads();
    if (t < 8) {
        float r = red[t];
#pragma unroll
        for (int o = 4; o; o >>= 1) r += __shfl_xor_sync(0x000000ffu, r, o);
        if (t == 0) stat[1] = rsqrtf(r * (1.0f / CDIM) + 1e-5f);
    }
    __syncthreads();

    out[i] = dlt * stat[1] * g[t] + be[t];
}

// ---------------------------------------------------------------------------
// Launch
// ---------------------------------------------------------------------------
extern "C" void kernel_launch(void* const* d_in, const int* in_sizes, int n_in,
                              void* d_out, int out_size)
{
    const float* query = (const float*)d_in[0];
    const float* src   = (const float*)d_in[1];
    const float* refp  = (const float*)d_in[2];
    // d_in[3] = spatial_shapes (int64, fixed 100x100), d_in[4] = level_start_index (unused)
    const float* W_off = (const float*)d_in[5];
    const float* b_off = (const float*)d_in[6];
    const float* W_aw  = (const float*)d_in[7];
    const float* b_aw  = (const float*)d_in[8];
    const float* W_val = (const float*)d_in[9];
    const float* b_val = (const float*)d_in[10];
    const float* W_out = (const float*)d_in[11];
    const float* b_out = (const float*)d_in[12];
    const float* g1    = (const float*)d_in[13];
    const float* be1   = (const float*)d_in[14];
    const float* W1    = (const float*)d_in[15];
    const float* b1    = (const float*)d_in[16];
    const float* W2    = (const float*)d_in[17];
    const float* b2    = (const float*)d_in[18];
    const float* g2    = (const float*)d_in[19];
    const float* be2   = (const float*)d_in[20];
    float* out = (float*)d_out;

    float *p_value, *p_off, *p_aw, *p_attn, *p_tmp, *p_q2, *p_ffn;
    cudaGetSymbolAddress((void**)&p_value, g_value);
    cudaGetSymbolAddress((void**)&p_off,   g_off);
    cudaGetSymbolAddress((void**)&p_aw,    g_aw);
    cudaGetSymbolAddress((void**)&p_attn,  g_attn);
    cudaGetSymbolAddress((void**)&p_tmp,   g_tmp);
    cudaGetSymbolAddress((void**)&p_q2,    g_q2);
    cudaGetSymbolAddress((void**)&p_ffn,   g_ffn);

    const dim3 blk(256);
    const int MB = MTOK / BM;  // 625

    // 1. value projection
    gemm_kernel<<<dim3(CDIM / BN, MB), blk>>>(src, W_val, b_val, p_value, CDIM, CDIM, 0);
    // 2. offset / attention-weight projections
    gemm_kernel<<<dim3(1, MB), blk>>>(query, W_off, b_off, p_off, 64, CDIM, 0);
    gemm_kernel<<<dim3(1, MB), blk>>>(query, W_aw,  b_aw,  p_aw,  32, CDIM, 0);
    // 3. bilinear sampling + weighted sum
    sample_kernel<<<MTOK, blk>>>(refp, p_attn);
    // 4. output projection + residual + LN
    gemm_kernel<<<dim3(CDIM / BN, MB), blk>>>(p_attn, W_out, b_out, p_tmp, CDIM, CDIM, 0);
    add_ln_kernel<<<MTOK, blk>>>(query, p_tmp, g1, be1, p_q2);
    // 5. FFN + residual + LN
    gemm_kernel<<<dim3(DFF / BN, MB), blk>>>(p_q2, W1, b1, p_ffn, DFF, CDIM, 1);
    gemm_kernel<<<dim3(CDIM / BN, MB), blk>>>(p_ffn, W2, b2, p_tmp, CDIM, DFF, 0);
    add_ln_kernel<<<MTOK, blk>>>(p_q2, p_tmp, g2, be2, out);
}

// round 2
// speedup vs baseline: 1.7501x; 1.7501x over previous
#include <cuda_runtime.h>
#include <cstdint>

#define DEV_INLINE __device__ __forceinline__

constexpr int BB   = 8;
constexpr int LQ   = 10000;
constexpr int CDIM = 256;
constexpr int NHD  = 8;
constexpr int NPT  = 4;
constexpr int DFF  = 1024;
constexpr int HIMG = 100;
constexpr int WIMG = 100;
constexpr int HD   = 32;
constexpr int MTOK = BB * LQ;  // 80000

__device__ float g_value[MTOK * CDIM];
__device__ float g_off  [MTOK * NHD * NPT * 2];
__device__ float g_aw   [MTOK * NHD * NPT];
__device__ float g_attn [MTOK * CDIM];
__device__ float g_tmp  [MTOK * CDIM];
__device__ float g_q2   [MTOK * CDIM];
__device__ float g_ffn  [MTOK * DFF];

// ---------------------------------------------------------------------------
// TF32 tensor-core GEMM: C[M,N] = A[M,K] @ B[K,N] + bias (+relu)
// Block tile 128x128x16, 8 warps, warp tile 64x32, mma.m16n8k8.tf32.
// A and B staged in smem as [dim][k] with stride 20 (conflict-free fragment LDS).
// ---------------------------------------------------------------------------
constexpr int BM = 128, BN = 128, BK = 16;
constexpr int SSTR = 20;  // smem row stride (floats): 16 + 4 pad

DEV_INLINE uint32_t f2tf32(float x) {
    uint32_t u;
    asm("cvt.rna.tf32.f32 %0, %1;" : "=r"(u) : "f"(x));
    return u;
}

DEV_INLINE void mma_tf32(float* d, const uint32_t* a, const uint32_t* b) {
    asm volatile(
        "mma.sync.aligned.m16n8k8.row.col.f32.tf32.tf32.f32 "
        "{%0,%1,%2,%3}, {%4,%5,%6,%7}, {%8,%9}, {%0,%1,%2,%3};\n"
        : "+f"(d[0]), "+f"(d[1]), "+f"(d[2]), "+f"(d[3])
        : "r"(a[0]), "r"(a[1]), "r"(a[2]), "r"(a[3]), "r"(b[0]), "r"(b[1]));
}

__global__ __launch_bounds__(256) void gemm_tf32_kernel(
    const float* __restrict__ A, const float* __restrict__ Bmat,
    const float* __restrict__ bias, float* __restrict__ C,
    int N, int K, int relu)
{
    __shared__ uint32_t As[2][BM * SSTR];
    __shared__ uint32_t Bs[2][BN * SSTR];

    const int tid  = threadIdx.x;
    const int lane = tid & 31;
    const int wid  = tid >> 5;
    const int wm   = wid >> 2;   // 0..1
    const int wn   = wid & 3;    // 0..3
    const size_t mbase = (size_t)blockIdx.y * BM;
    const int    nbase = blockIdx.x * BN;

    // global-load addressing
    const int aRow = tid >> 2;          // 0..63 (+64)
    const int aCol = (tid & 3) << 2;    // 0,4,8,12
    const int bRow = tid >> 5;          // 0..7  (+8)
    const int bCol = (tid & 31) << 2;   // 0..124

    const float* Ab = A + mbase * (size_t)K;

    float acc[4][4][4];
#pragma unroll
    for (int mi = 0; mi < 4; ++mi)
#pragma unroll
        for (int ni = 0; ni < 4; ++ni)
#pragma unroll
            for (int j = 0; j < 4; ++j) acc[mi][ni][j] = 0.f;

    float4 pa[2], pb[2];

    // ---- prefetch tile 0 ----
#pragma unroll
    for (int i = 0; i < 2; ++i)
        pa[i] = *(const float4*)(Ab + (size_t)(aRow + 64 * i) * K + aCol);
#pragma unroll
    for (int i = 0; i < 2; ++i) {
        int col = nbase + bCol;
        const float* bp = Bmat + (size_t)(bRow + 8 * i) * N;
        float4 v = {0.f, 0.f, 0.f, 0.f};
        if (col + 3 < N) v = *(const float4*)(bp + col);
        else {
            if (col + 0 < N) v.x = bp[col + 0];
            if (col + 1 < N) v.y = bp[col + 1];
            if (col + 2 < N) v.z = bp[col + 2];
        }
        pb[i] = v;
    }
    // ---- store tile 0 ----
#pragma unroll
    for (int i = 0; i < 2; ++i) {
        uint32_t* dst = &As[0][(aRow + 64 * i) * SSTR + aCol];
        dst[0] = f2tf32(pa[i].x); dst[1] = f2tf32(pa[i].y);
        dst[2] = f2tf32(pa[i].z); dst[3] = f2tf32(pa[i].w);
    }
#pragma unroll
    for (int i = 0; i < 2; ++i) {
        int r = bRow + 8 * i;
        Bs[0][(bCol + 0) * SSTR + r] = f2tf32(pb[i].x);
        Bs[0][(bCol + 1) * SSTR + r] = f2tf32(pb[i].y);
        Bs[0][(bCol + 2) * SSTR + r] = f2tf32(pb[i].z);
        Bs[0][(bCol + 3) * SSTR + r] = f2tf32(pb[i].w);
    }
    __syncthreads();

    const int rA = wm * 64 + (lane >> 2);  // fragment row base
    const int cA = lane & 3;               // fragment k base
    const int cB = wn * 32 + (lane >> 2);  // fragment col base

    int cur = 0;
    for (int k0 = 0; k0 < K; k0 += BK) {
        const bool has_next = (k0 + BK) < K;
        if (has_next) {
            const int kn = k0 + BK;
#pragma unroll
            for (int i = 0; i < 2; ++i)
                pa[i] = *(const float4*)(Ab + (size_t)(aRow + 64 * i) * K + kn + aCol);
#pragma unroll
            for (int i = 0; i < 2; ++i) {
                int col = nbase + bCol;
                const float* bp = Bmat + (size_t)(kn + bRow + 8 * i) * N;
                float4 v = {0.f, 0.f, 0.f, 0.f};
                if (col + 3 < N) v = *(const float4*)(bp + col);
                else {
                    if (col + 0 < N) v.x = bp[col + 0];
                    if (col + 1 < N) v.y = bp[col + 1];
                    if (col + 2 < N) v.z = bp[col + 2];
                }
                pb[i] = v;
            }
        }

        // ---- compute on buffer `cur` ----
#pragma unroll
        for (int kk = 0; kk < BK; kk += 8) {
            uint32_t afr[4][4], bfr[4][2];
#pragma unroll
            for (int mi = 0; mi < 4; ++mi) {
                const uint32_t* base = &As[cur][(rA + mi * 16) * SSTR + kk + cA];
                afr[mi][0] = base[0];
                afr[mi][1] = base[8 * SSTR];
                afr[mi][2] = base[4];
                afr[mi][3] = base[8 * SSTR + 4];
            }
#pragma unroll
            for (int ni = 0; ni < 4; ++ni) {
                const uint32_t* base = &Bs[cur][(cB + ni * 8) * SSTR + kk + cA];
                bfr[ni][0] = base[0];
                bfr[ni][1] = base[4];
            }
#pragma unroll
            for (int mi = 0; mi < 4; ++mi)
#pragma unroll
                for (int ni = 0; ni < 4; ++ni)
                    mma_tf32(acc[mi][ni], afr[mi], bfr[ni]);
        }

        if (has_next) {
            const int nxt = cur ^ 1;
#pragma unroll
            for (int i = 0; i < 2; ++i) {
                uint32_t* dst = &As[nxt][(aRow + 64 * i) * SSTR + aCol];
                dst[0] = f2tf32(pa[i].x); dst[1] = f2tf32(pa[i].y);
                dst[2] = f2tf32(pa[i].z); dst[3] = f2tf32(pa[i].w);
            }
#pragma unroll
            for (int i = 0; i < 2; ++i) {
                int r = bRow + 8 * i;
                Bs[nxt][(bCol + 0) * SSTR + r] = f2tf32(pb[i].x);
                Bs[nxt][(bCol + 1) * SSTR + r] = f2tf32(pb[i].y);
                Bs[nxt][(bCol + 2) * SSTR + r] = f2tf32(pb[i].z);
                Bs[nxt][(bCol + 3) * SSTR + r] = f2tf32(pb[i].w);
            }
            __syncthreads();
            cur = nxt;
        }
    }

    // ---- epilogue ----
#pragma unroll
    for (int mi = 0; mi < 4; ++mi) {
#pragma unroll
        for (int ni = 0; ni < 4; ++ni) {
            int col = nbase + wn * 32 + ni * 8 + (lane & 3) * 2;
            if (col >= N) continue;
            size_t r0 = mbase + wm * 64 + mi * 16 + (lane >> 2);
            size_t r1 = r0 + 8;
            float b0 = bias[col];
            float b1 = (col + 1 < N) ? bias[col + 1] : 0.f;
            float v0 = acc[mi][ni][0] + b0;
            float v1 = acc[mi][ni][1] + b1;
            float v2 = acc[mi][ni][2] + b0;
            float v3 = acc[mi][ni][3] + b1;
            if (relu) {
                v0 = fmaxf(v0, 0.f); v1 = fmaxf(v1, 0.f);
                v2 = fmaxf(v2, 0.f); v3 = fmaxf(v3, 0.f);
            }
            C[r0 * (size_t)N + col] = v0;
            C[r1 * (size_t)N + col] = v2;
            if (col + 1 < N) {
                C[r0 * (size_t)N + col + 1] = v1;
                C[r1 * (size_t)N + col + 1] = v3;
            }
        }
    }
}

// ---------------------------------------------------------------------------
// Bilinear sampling + softmax(aw) + einsum -> attn
// ---------------------------------------------------------------------------
DEV_INLINE float corner_val(const float* __restrict__ vb, int x, int y, float w)
{
    if (x < 0 || x >= WIMG || y < 0 || y >= HIMG) return 0.f;
    return vb[(size_t)(y * WIMG + x) * CDIM] * w;
}

__global__ __launch_bounds__(256) void sample_kernel(
    const float* __restrict__ refp, float* __restrict__ attn)
{
    __shared__ float s_loc[NHD * NPT * 2];
    __shared__ float s_aw[NHD * NPT];

    const int token = blockIdx.x;
    const int b     = token / LQ;
    const int tid   = threadIdx.x;

    if (tid < 32) {
        const int idx = tid;
        float ox = g_off[(size_t)token * 64 + idx * 2 + 0];
        float oy = g_off[(size_t)token * 64 + idx * 2 + 1];
        float rx = refp[(size_t)token * 2 + 0];
        float ry = refp[(size_t)token * 2 + 1];
        s_loc[idx * 2 + 0] = rx + ox * (1.0f / WIMG);
        s_loc[idx * 2 + 1] = ry + oy * (1.0f / HIMG);

        float logit = g_aw[(size_t)token * 32 + idx];
        float mx = logit;
        mx = fmaxf(mx, __shfl_xor_sync(0xffffffffu, mx, 1));
        mx = fmaxf(mx, __shfl_xor_sync(0xffffffffu, mx, 2));
        float e = __expf(logit - mx);
        float s = e;
        s += __shfl_xor_sync(0xffffffffu, s, 1);
        s += __shfl_xor_sync(0xffffffffu, s, 2);
        s_aw[idx] = e / s;
    }
    __syncthreads();

    const int h = tid >> 5;
    const int d = tid & 31;
    const float* vb = g_value + (size_t)b * LQ * CDIM + h * HD + d;

    float acc = 0.f;
#pragma unroll
    for (int p = 0; p < NPT; ++p) {
        float x = s_loc[(h * NPT + p) * 2 + 0] * WIMG - 0.5f;
        float y = s_loc[(h * NPT + p) * 2 + 1] * HIMG - 0.5f;
        float x0f = floorf(x), y0f = floorf(y);
        float fx = x - x0f, fy = y - y0f;
        int x0 = (int)x0f, y0 = (int)y0f;
        float a = s_aw[h * NPT + p];
        float w00 = a * (1.f - fx) * (1.f - fy);
        float w10 = a * fx * (1.f - fy);
        float w01 = a * (1.f - fx) * fy;
        float w11 = a * fx * fy;
        acc += corner_val(vb, x0,     y0,     w00);
        acc += corner_val(vb, x0 + 1, y0,     w10);
        acc += corner_val(vb, x0,     y0 + 1, w01);
        acc += corner_val(vb, x0 + 1, y0 + 1, w11);
    }
    attn[(size_t)token * CDIM + h * HD + d] = acc;
}

// ---------------------------------------------------------------------------
// Fused residual + LayerNorm
// ---------------------------------------------------------------------------
__global__ __launch_bounds__(256) void add_ln_kernel(
    const float* __restrict__ x, const float* __restrict__ y,
    const float* __restrict__ g, const float* __restrict__ be,
    float* __restrict__ out)
{
    const int row = blockIdx.x;
    const int t   = threadIdx.x;
    __shared__ float red[8];
    __shared__ float stat[2];

    size_t i = (size_t)row * CDIM + t;
    float v = x[i] + y[i];

    float s = v;
#pragma unroll
    for (int o = 16; o; o >>= 1) s += __shfl_xor_sync(0xffffffffu, s, o);
    if ((t & 31) == 0) red[t >> 5] = s;
    __syncthreads();
    if (t < 8) {
        float r = red[t];
#pragma unroll
        for (int o = 4; o; o >>= 1) r += __shfl_xor_sync(0x000000ffu, r, o);
        if (t == 0) stat[0] = r * (1.0f / CDIM);
    }
    __syncthreads();
    float m   = stat[0];
    float dlt = v - m;

    float s2 = dlt * dlt;
#pragma unroll
    for (int o = 16; o; o >>= 1) s2 += __shfl_xor_sync(0xffffffffu, s2, o);
    if ((t & 31) == 0) red[t >> 5] = s2;
    __syncthreads();
    if (t < 8) {
        float r = red[t];
#pragma unroll
        for (int o = 4; o; o >>= 1) r += __shfl_xor_sync(0x000000ffu, r, o);
        if (t == 0) stat[1] = rsqrtf(r * (1.0f / CDIM) + 1e-5f);
    }
    __syncthreads();

    out[i] = dlt * stat[1] * g[t] + be[t];
}

// ---------------------------------------------------------------------------
// Launch
// ---------------------------------------------------------------------------
extern "C" void kernel_launch(void* const* d_in, const int* in_sizes, int n_in,
                              void* d_out, int out_size)
{
    const float* query = (const float*)d_in[0];
    const float* src   = (const float*)d_in[1];
    const float* refp  = (const float*)d_in[2];
    const float* W_off = (const float*)d_in[5];
    const float* b_off = (const float*)d_in[6];
    const float* W_aw  = (const float*)d_in[7];
    const float* b_aw  = (const float*)d_in[8];
    const float* W_val = (const float*)d_in[9];
    const float* b_val = (const float*)d_in[10];
    const float* W_out = (const float*)d_in[11];
    const float* b_out = (const float*)d_in[12];
    const float* g1    = (const float*)d_in[13];
    const float* be1   = (const float*)d_in[14];
    const float* W1    = (const float*)d_in[15];
    const float* b1    = (const float*)d_in[16];
    const float* W2    = (const float*)d_in[17];
    const float* b2    = (const float*)d_in[18];
    const float* g2    = (const float*)d_in[19];
    const float* be2   = (const float*)d_in[20];
    float* out = (float*)d_out;

    float *p_value, *p_off, *p_aw, *p_attn, *p_tmp, *p_q2, *p_ffn;
    cudaGetSymbolAddress((void**)&p_value, g_value);
    cudaGetSymbolAddress((void**)&p_off,   g_off);
    cudaGetSymbolAddress((void**)&p_aw,    g_aw);
    cudaGetSymbolAddress((void**)&p_attn,  g_attn);
    cudaGetSymbolAddress((void**)&p_tmp,   g_tmp);
    cudaGetSymbolAddress((void**)&p_q2,    g_q2);
    cudaGetSymbolAddress((void**)&p_ffn,   g_ffn);

    const dim3 blk(256);
    const int MB = MTOK / BM;  // 625

    gemm_tf32_kernel<<<dim3(CDIM / BN, MB), blk>>>(src, W_val, b_val, p_value, CDIM, CDIM, 0);
    gemm_tf32_kernel<<<dim3(1, MB), blk>>>(query, W_off, b_off, p_off, 64, CDIM, 0);
    gemm_tf32_kernel<<<dim3(1, MB), blk>>>(query, W_aw,  b_aw,  p_aw,  32, CDIM, 0);
    sample_kernel<<<MTOK, blk>>>(refp, p_attn);
    gemm_tf32_kernel<<<dim3(CDIM / BN, MB), blk>>>(p_attn, W_out, b_out, p_tmp, CDIM, CDIM, 0);
    add_ln_kernel<<<MTOK, blk>>>(query, p_tmp, g1, be1, p_q2);
    gemm_tf32_kernel<<<dim3(DFF / BN, MB), blk>>>(p_q2, W1, b1, p_ffn, DFF, CDIM, 1);
    gemm_tf32_kernel<<<dim3(CDIM / BN, MB), blk>>>(p_ffn, W2, b2, p_tmp, CDIM, DFF, 0);
    add_ln_kernel<<<MTOK, blk>>>(p_q2, p_tmp, g2, be2, out);
}

// round 3
// speedup vs baseline: 3.0909x; 1.7662x over previous
#include <cuda_runtime.h>
#include <cstdint>

#define DEV_INLINE __device__ __forceinline__

constexpr int BB   = 8;
constexpr int LQ   = 10000;
constexpr int CDIM = 256;
constexpr int NHD  = 8;
constexpr int NPT  = 4;
constexpr int DFF  = 1024;
constexpr int HIMG = 100;
constexpr int WIMG = 100;
constexpr int HD   = 32;
constexpr int MTOK = BB * LQ;  // 80000
constexpr int NOFFAW = 96;     // 64 (off) + 32 (aw)

__device__ float g_value[MTOK * CDIM];
__device__ float g_offaw[MTOK * NOFFAW];
__device__ float g_attn [MTOK * CDIM];
__device__ float g_tmp  [MTOK * CDIM];
__device__ float g_q2   [MTOK * CDIM];
__device__ float g_ffn  [MTOK * DFF];
__device__ float g_Wcat [CDIM * NOFFAW];
__device__ float g_bcat [NOFFAW];

// ---------------------------------------------------------------------------
// TF32 tensor-core GEMM with cp.async 4-stage pipeline.
// C[M,N] = A[M,K] @ B[K,N] + bias (+relu)
// Block 128x128x16, 8 warps (64x32 each), mma.m16n8k8.tf32 fed raw f32 bits.
// A smem: [row][k] stride 20 (conflict-free). B smem: [k][n] stride 136.
// ---------------------------------------------------------------------------
constexpr int BM = 128, BN = 128, BK = 16;
constexpr int SA = 20;    // A smem row stride (floats)
constexpr int SB = 136;   // B smem row stride (floats)
constexpr int STAGES = 4;
constexpr int STAGE_U32 = BM * SA + BK * SB;          // 4736
constexpr int GEMM_SMEM = STAGES * STAGE_U32 * 4;     // 75776 bytes

DEV_INLINE void mma_tf32(float* d, const uint32_t* a, const uint32_t* b) {
    asm volatile(
        "mma.sync.aligned.m16n8k8.row.col.f32.tf32.tf32.f32 "
        "{%0,%1,%2,%3}, {%4,%5,%6,%7}, {%8,%9}, {%0,%1,%2,%3};\n"
        : "+f"(d[0]), "+f"(d[1]), "+f"(d[2]), "+f"(d[3])
        : "r"(a[0]), "r"(a[1]), "r"(a[2]), "r"(a[3]), "r"(b[0]), "r"(b[1]));
}

DEV_INLINE void cp_async16(uint32_t dst, const void* src, int src_bytes) {
    asm volatile("cp.async.cg.shared.global [%0], [%1], 16, %2;\n"
                 :: "r"(dst), "l"(src), "r"(src_bytes));
}

__global__ __launch_bounds__(256) void gemm_tf32_kernel(
    const float* __restrict__ A, const float* __restrict__ Bmat,
    const float* __restrict__ bias, float* __restrict__ C,
    int N, int K, int relu)
{
    extern __shared__ uint32_t smem[];

    const int tid  = threadIdx.x;
    const int lane = tid & 31;
    const int wid  = tid >> 5;
    const int wm   = wid >> 2;   // 0..1
    const int wn   = wid & 3;    // 0..3
    const size_t mbase = (size_t)blockIdx.y * BM;
    const int    nbase = blockIdx.x * BN;

    const int aRow = tid >> 2;          // 0..63 (+64)
    const int aCol = (tid & 3) << 2;    // 0,4,8,12
    const int bRow = tid >> 5;          // 0..7  (+8)
    const int bCol = (tid & 31) << 2;   // 0..124

    const float* Ab = A + mbase * (size_t)K;

    // per-thread cp.async source/dest precompute
    const int colg   = nbase + bCol;
    const int bbytes = max(0, min(16, (N - colg) * 4));
    const int colc   = min(colg, N - 4);   // clamped valid address

    uint32_t sbase = (uint32_t)__cvta_generic_to_shared(smem);

    float acc[4][4][4];
#pragma unroll
    for (int mi = 0; mi < 4; ++mi)
#pragma unroll
        for (int ni = 0; ni < 4; ++ni)
#pragma unroll
            for (int j = 0; j < 4; ++j) acc[mi][ni][j] = 0.f;

    const int nsteps = K / BK;

    // ---- tile loader ----
    auto load_tile = [&](int stage, int k0) {
        uint32_t sA = sbase + stage * (STAGE_U32 * 4);
        uint32_t sB = sA + BM * SA * 4;
#pragma unroll
        for (int i = 0; i < 2; ++i) {
            int r = aRow + 64 * i;
            cp_async16(sA + (r * SA + aCol) * 4,
                       Ab + (size_t)r * K + k0 + aCol, 16);
        }
#pragma unroll
        for (int i = 0; i < 2; ++i) {
            int kb = bRow + 8 * i;
            cp_async16(sB + (kb * SB + bCol) * 4,
                       Bmat + (size_t)(k0 + kb) * N + colc, bbytes);
        }
    };

    // ---- prologue: fill STAGES-1 stages ----
#pragma unroll
    for (int s = 0; s < STAGES - 1; ++s) {
        if (s < nsteps) load_tile(s, s * BK);
        asm volatile("cp.async.commit_group;\n");
    }
    asm volatile("cp.async.wait_group %0;\n" :: "n"(STAGES - 2));
    __syncthreads();

    const int rA = wm * 64 + (lane >> 2);
    const int cA = lane & 3;
    const int cB = wn * 32 + (lane >> 2);

    int read_stage = 0, write_stage = STAGES - 1;

    for (int i = 0; i < nsteps; ++i) {
        const uint32_t* As = smem + read_stage * STAGE_U32;
        const uint32_t* Bs = As + BM * SA;

        // ---- compute BK=16 (two k=8 steps) ----
#pragma unroll
        for (int kk = 0; kk < BK; kk += 8) {
            uint32_t afr[4][4], bfr[4][2];
#pragma unroll
            for (int mi = 0; mi < 4; ++mi) {
                const uint32_t* base = &As[(rA + mi * 16) * SA + kk + cA];
                afr[mi][0] = base[0];
                afr[mi][1] = base[8 * SA];
                afr[mi][2] = base[4];
                afr[mi][3] = base[8 * SA + 4];
            }
#pragma unroll
            for (int ni = 0; ni < 4; ++ni) {
                const uint32_t* base = &Bs[(kk + cA) * SB + cB + ni * 8];
                bfr[ni][0] = base[0];
                bfr[ni][1] = base[4 * SB];
            }
#pragma unroll
            for (int mi = 0; mi < 4; ++mi)
#pragma unroll
                for (int ni = 0; ni < 4; ++ni)
                    mma_tf32(acc[mi][ni], afr[mi], bfr[ni]);
        }

        // ---- issue next load ----
        if (i + STAGES - 1 < nsteps)
            load_tile(write_stage, (i + STAGES - 1) * BK);
        asm volatile("cp.async.commit_group;\n");
        asm volatile("cp.async.wait_group %0;\n" :: "n"(STAGES - 2));
        __syncthreads();

        read_stage  = (read_stage + 1) & (STAGES - 1);
        write_stage = (write_stage + 1) & (STAGES - 1);
    }

    // ---- epilogue ----
#pragma unroll
    for (int mi = 0; mi < 4; ++mi) {
#pragma unroll
        for (int ni = 0; ni < 4; ++ni) {
            int col = nbase + wn * 32 + ni * 8 + (lane & 3) * 2;
            if (col >= N) continue;
            size_t r0 = mbase + wm * 64 + mi * 16 + (lane >> 2);
            size_t r1 = r0 + 8;
            float b0 = bias[col];
            float b1 = (col + 1 < N) ? bias[col + 1] : 0.f;
            float v0 = acc[mi][ni][0] + b0;
            float v1 = acc[mi][ni][1] + b1;
            float v2 = acc[mi][ni][2] + b0;
            float v3 = acc[mi][ni][3] + b1;
            if (relu) {
                v0 = fmaxf(v0, 0.f); v1 = fmaxf(v1, 0.f);
                v2 = fmaxf(v2, 0.f); v3 = fmaxf(v3, 0.f);
            }
            C[r0 * (size_t)N + col] = v0;
            C[r1 * (size_t)N + col] = v2;
            if (col + 1 < N) {
                C[r0 * (size_t)N + col + 1] = v1;
                C[r1 * (size_t)N + col + 1] = v3;
            }
        }
    }
}

// ---------------------------------------------------------------------------
// Concat W_off|W_aw -> g_Wcat, b_off|b_aw -> g_bcat
// ---------------------------------------------------------------------------
__global__ void concat_w_kernel(const float* __restrict__ W_off,
                                const float* __restrict__ b_off,
                                const float* __restrict__ W_aw,
                                const float* __restrict__ b_aw)
{
    int i = blockIdx.x * blockDim.x + threadIdx.x;
    if (i < CDIM * NOFFAW) {
        int k = i / NOFFAW, n = i % NOFFAW;
        g_Wcat[i] = (n < 64) ? W_off[k * 64 + n] : W_aw[k * 32 + (n - 64)];
    }
    if (i < NOFFAW)
        g_bcat[i] = (i < 64) ? b_off[i] : b_aw[i - 64];
}

// ---------------------------------------------------------------------------
// Bilinear sampling + softmax(aw) + einsum -> attn
// ---------------------------------------------------------------------------
DEV_INLINE float corner_val(const float* __restrict__ vb, int x, int y, float w)
{
    if (x < 0 || x >= WIMG || y < 0 || y >= HIMG) return 0.f;
    return vb[(size_t)(y * WIMG + x) * CDIM] * w;
}

__global__ __launch_bounds__(256) void sample_kernel(
    const float* __restrict__ refp, float* __restrict__ attn)
{
    __shared__ float s_loc[NHD * NPT * 2];
    __shared__ float s_aw[NHD * NPT];

    const int token = blockIdx.x;
    const int b     = token / LQ;
    const int tid   = threadIdx.x;

    if (tid < 32) {
        const int idx = tid;
        float ox = g_offaw[(size_t)token * NOFFAW + idx * 2 + 0];
        float oy = g_offaw[(size_t)token * NOFFAW + idx * 2 + 1];
        float rx = refp[(size_t)token * 2 + 0];
        float ry = refp[(size_t)token * 2 + 1];
        s_loc[idx * 2 + 0] = rx + ox * (1.0f / WIMG);
        s_loc[idx * 2 + 1] = ry + oy * (1.0f / HIMG);

        float logit = g_offaw[(size_t)token * NOFFAW + 64 + idx];
        float mx = logit;
        mx = fmaxf(mx, __shfl_xor_sync(0xffffffffu, mx, 1));
        mx = fmaxf(mx, __shfl_xor_sync(0xffffffffu, mx, 2));
        float e = __expf(logit - mx);
        float s = e;
        s += __shfl_xor_sync(0xffffffffu, s, 1);
        s += __shfl_xor_sync(0xffffffffu, s, 2);
        s_aw[idx] = e / s;
    }
    __syncthreads();

    const int h = tid >> 5;
    const int d = tid & 31;
    const float* vb = g_value + (size_t)b * LQ * CDIM + h * HD + d;

    float acc = 0.f;
#pragma unroll
    for (int p = 0; p < NPT; ++p) {
        float x = s_loc[(h * NPT + p) * 2 + 0] * WIMG - 0.5f;
        float y = s_loc[(h * NPT + p) * 2 + 1] * HIMG - 0.5f;
        float x0f = floorf(x), y0f = floorf(y);
        float fx = x - x0f, fy = y - y0f;
        int x0 = (int)x0f, y0 = (int)y0f;
        float a = s_aw[h * NPT + p];
        float w00 = a * (1.f - fx) * (1.f - fy);
        float w10 = a * fx * (1.f - fy);
        float w01 = a * (1.f - fx) * fy;
        float w11 = a * fx * fy;
        acc += corner_val(vb, x0,     y0,     w00);
        acc += corner_val(vb, x0 + 1, y0,     w10);
        acc += corner_val(vb, x0,     y0 + 1, w01);
        acc += corner_val(vb, x0 + 1, y0 + 1, w11);
    }
    attn[(size_t)token * CDIM + h * HD + d] = acc;
}

// ---------------------------------------------------------------------------
// Fused residual + LayerNorm
// ---------------------------------------------------------------------------
__global__ __launch_bounds__(256) void add_ln_kernel(
    const float* __restrict__ x, const float* __restrict__ y,
    const float* __restrict__ g, const float* __restrict__ be,
    float* __restrict__ out)
{
    const int row = blockIdx.x;
    const int t   = threadIdx.x;
    __shared__ float red[8];
    __shared__ float stat[2];

    size_t i = (size_t)row * CDIM + t;
    float v = x[i] + y[i];

    float s = v;
#pragma unroll
    for (int o = 16; o; o >>= 1) s += __shfl_xor_sync(0xffffffffu, s, o);
    if ((t & 31) == 0) red[t >> 5] = s;
    __syncthreads();
    if (t < 8) {
        float r = red[t];
#pragma unroll
        for (int o = 4; o; o >>= 1) r += __shfl_xor_sync(0x000000ffu, r, o);
        if (t == 0) stat[0] = r * (1.0f / CDIM);
    }
    __syncthreads();
    float m   = stat[0];
    float dlt = v - m;

    float s2 = dlt * dlt;
#pragma unroll
    for (int o = 16; o; o >>= 1) s2 += __shfl_xor_sync(0xffffffffu, s2, o);
    if ((t & 31) == 0) red[t >> 5] = s2;
    __syncthreads();
    if (t < 8) {
        float r = red[t];
#pragma unroll
        for (int o = 4; o; o >>= 1) r += __shfl_xor_sync(0x000000ffu, r, o);
        if (t == 0) stat[1] = rsqrtf(r * (1.0f / CDIM) + 1e-5f);
    }
    __syncthreads();

    out[i] = dlt * stat[1] * g[t] + be[t];
}

// ---------------------------------------------------------------------------
// Launch
// ---------------------------------------------------------------------------
extern "C" void kernel_launch(void* const* d_in, const int* in_sizes, int n_in,
                              void* d_out, int out_size)
{
    const float* query = (const float*)d_in[0];
    const float* src   = (const float*)d_in[1];
    const float* refp  = (const float*)d_in[2];
    const float* W_off = (const float*)d_in[5];
    const float* b_off = (const float*)d_in[6];
    const float* W_aw  = (const float*)d_in[7];
    const float* b_aw  = (const float*)d_in[8];
    const float* W_val = (const float*)d_in[9];
    const float* b_val = (const float*)d_in[10];
    const float* W_out = (const float*)d_in[11];
    const float* b_out = (const float*)d_in[12];
    const float* g1    = (const float*)d_in[13];
    const float* be1   = (const float*)d_in[14];
    const float* W1    = (const float*)d_in[15];
    const float* b1    = (const float*)d_in[16];
    const float* W2    = (const float*)d_in[17];
    const float* b2    = (const float*)d_in[18];
    const float* g2    = (const float*)d_in[19];
    const float* be2   = (const float*)d_in[20];
    float* out = (float*)d_out;

    float *p_value, *p_offaw, *p_attn, *p_tmp, *p_q2, *p_ffn, *p_Wcat, *p_bcat;
    cudaGetSymbolAddress((void**)&p_value, g_value);
    cudaGetSymbolAddress((void**)&p_offaw, g_offaw);
    cudaGetSymbolAddress((void**)&p_attn,  g_attn);
    cudaGetSymbolAddress((void**)&p_tmp,   g_tmp);
    cudaGetSymbolAddress((void**)&p_q2,    g_q2);
    cudaGetSymbolAddress((void**)&p_ffn,   g_ffn);
    cudaGetSymbolAddress((void**)&p_Wcat,  g_Wcat);
    cudaGetSymbolAddress((void**)&p_bcat,  g_bcat);

    cudaFuncSetAttribute(gemm_tf32_kernel,
                         cudaFuncAttributeMaxDynamicSharedMemorySize, GEMM_SMEM);

    const dim3 blk(256);
    const int MB = MTOK / BM;  // 625

    concat_w_kernel<<<(CDIM * NOFFAW + 255) / 256, blk>>>(W_off, b_off, W_aw, b_aw);
    gemm_tf32_kernel<<<dim3(CDIM / BN, MB), blk, GEMM_SMEM>>>(src, W_val, b_val, p_value, CDIM, CDIM, 0);
    gemm_tf32_kernel<<<dim3(1, MB), blk, GEMM_SMEM>>>(query, p_Wcat, p_bcat, p_offaw, NOFFAW, CDIM, 0);
    sample_kernel<<<MTOK, blk>>>(refp, p_attn);
    gemm_tf32_kernel<<<dim3(CDIM / BN, MB), blk, GEMM_SMEM>>>(p_attn, W_out, b_out, p_tmp, CDIM, CDIM, 0);
    add_ln_kernel<<<MTOK, blk>>>(query, p_tmp, g1, be1, p_q2);
    gemm_tf32_kernel<<<dim3(DFF / BN, MB), blk, GEMM_SMEM>>>(p_q2, W1, b1, p_ffn, DFF, CDIM, 1);
    gemm_tf32_kernel<<<dim3(CDIM / BN, MB), blk, GEMM_SMEM>>>(p_ffn, W2, b2, p_tmp, CDIM, DFF, 0);
    add_ln_kernel<<<MTOK, blk>>>(p_q2, p_tmp, g2, be2, out);
}

// round 4
// speedup vs baseline: 3.6098x; 1.1679x over previous
#include <cuda_runtime.h>
#include <cstdint>

#define DEV_INLINE __device__ __forceinline__

constexpr int BB   = 8;
constexpr int LQ   = 10000;
constexpr int CDIM = 256;
constexpr int NHD  = 8;
constexpr int NPT  = 4;
constexpr int DFF  = 1024;
constexpr int HIMG = 100;
constexpr int WIMG = 100;
constexpr int HD   = 32;
constexpr int MTOK = BB * LQ;  // 80000
constexpr int NOFFAW = 96;

__device__ float g_value[MTOK * CDIM];
__device__ float g_offaw[MTOK * NOFFAW];
__device__ float g_attn [MTOK * CDIM];
__device__ float g_tmp  [MTOK * CDIM];
__device__ float g_q2   [MTOK * CDIM];
__device__ float g_ffn  [MTOK * DFF];
__device__ float g_Wcat [CDIM * NOFFAW];
__device__ float g_bcat [NOFFAW];

// ---------------------------------------------------------------------------
// TF32 tensor-core GEMM, cp.async 4-stage pipeline, templated block-N.
// BN_=256: 8 warps as 2x4 grid of 64x64 warp tiles (MMA:LDS = 1:1).
// BN_=128: 8 warps as 2x4 grid of 64x32 warp tiles (for N=96 GEMM).
// ---------------------------------------------------------------------------
constexpr int BM = 128, BK = 16;
constexpr int SA = 20;                 // A smem row stride (u32)
constexpr int STAGES = 4;

DEV_INLINE void mma_tf32(float* d, const uint32_t* a, const uint32_t* b) {
    asm volatile(
        "mma.sync.aligned.m16n8k8.row.col.f32.tf32.tf32.f32 "
        "{%0,%1,%2,%3}, {%4,%5,%6,%7}, {%8,%9}, {%0,%1,%2,%3};\n"
        : "+f"(d[0]), "+f"(d[1]), "+f"(d[2]), "+f"(d[3])
        : "r"(a[0]), "r"(a[1]), "r"(a[2]), "r"(a[3]), "r"(b[0]), "r"(b[1]));
}

DEV_INLINE void cp_async16(uint32_t dst, const void* src, int src_bytes) {
    asm volatile("cp.async.cg.shared.global [%0], [%1], 16, %2;\n"
                 :: "r"(dst), "l"(src), "r"(src_bytes));
}

template<int BN_>
__global__ __launch_bounds__(256) void gemm_tf32_kernel(
    const float* __restrict__ A, const float* __restrict__ Bmat,
    const float* __restrict__ bias, float* __restrict__ C,
    int N, int K, int relu)
{
    constexpr int SB_  = BN_ + 8;                 // B smem row stride (u32)
    constexpr int WNT  = BN_ / 4;                 // warp n-tile (64 or 32)
    constexpr int NI   = WNT / 8;                 // 8 or 4
    constexpr int STAGE_U32 = BM * SA + BK * SB_;
    constexpr int TPR  = BN_ / 4;                 // threads per B row
    constexpr int RPP  = 256 / TPR;               // B rows per pass
    constexpr int BITER = BK / RPP;

    extern __shared__ uint32_t smem[];

    const int tid  = threadIdx.x;
    const int lane = tid & 31;
    const int wid  = tid >> 5;
    const int wm   = wid >> 2;
    const int wn   = wid & 3;
    const size_t mbase = (size_t)blockIdx.y * BM;
    const int    nbase = blockIdx.x * BN_;

    const int aRow = tid >> 2;
    const int aCol = (tid & 3) << 2;
    const int bRow0 = tid / TPR;
    const int bCol  = (tid % TPR) << 2;

    const float* Ab = A + mbase * (size_t)K;

    const int colg   = nbase + bCol;
    const int bbytes = max(0, min(16, (N - colg) * 4));
    const int colc   = min(colg, N - 4);

    uint32_t sbase = (uint32_t)__cvta_generic_to_shared(smem);

    float acc[4][NI][4];
#pragma unroll
    for (int mi = 0; mi < 4; ++mi)
#pragma unroll
        for (int ni = 0; ni < NI; ++ni)
#pragma unroll
            for (int j = 0; j < 4; ++j) acc[mi][ni][j] = 0.f;

    const int nsteps = K / BK;

    auto load_tile = [&](int stage, int k0) {
        uint32_t sA = sbase + stage * (STAGE_U32 * 4);
        uint32_t sB = sA + BM * SA * 4;
#pragma unroll
        for (int i = 0; i < 2; ++i) {
            int r = aRow + 64 * i;
            cp_async16(sA + (r * SA + aCol) * 4,
                       Ab + (size_t)r * K + k0 + aCol, 16);
        }
#pragma unroll
        for (int i = 0; i < BITER; ++i) {
            int kb = bRow0 + RPP * i;
            cp_async16(sB + (kb * SB_ + bCol) * 4,
                       Bmat + (size_t)(k0 + kb) * N + colc, bbytes);
        }
    };

#pragma unroll
    for (int s = 0; s < STAGES - 1; ++s) {
        if (s < nsteps) load_tile(s, s * BK);
        asm volatile("cp.async.commit_group;\n");
    }
    asm volatile("cp.async.wait_group %0;\n" :: "n"(STAGES - 2));
    __syncthreads();

    const int rA = wm * 64 + (lane >> 2);
    const int cA = lane & 3;
    const int cB = wn * WNT + (lane >> 2);

    int read_stage = 0, write_stage = STAGES - 1;

    for (int i = 0; i < nsteps; ++i) {
        const uint32_t* As = smem + read_stage * STAGE_U32;
        const uint32_t* Bs = As + BM * SA;

#pragma unroll
        for (int kk = 0; kk < BK; kk += 8) {
            uint32_t afr[4][4], bfr[NI][2];
#pragma unroll
            for (int mi = 0; mi < 4; ++mi) {
                const uint32_t* base = &As[(rA + mi * 16) * SA + kk + cA];
                afr[mi][0] = base[0];
                afr[mi][1] = base[8 * SA];
                afr[mi][2] = base[4];
                afr[mi][3] = base[8 * SA + 4];
            }
#pragma unroll
            for (int ni = 0; ni < NI; ++ni) {
                const uint32_t* base = &Bs[(kk + cA) * SB_ + cB + ni * 8];
                bfr[ni][0] = base[0];
                bfr[ni][1] = base[4 * SB_];
            }
#pragma unroll
            for (int mi = 0; mi < 4; ++mi)
#pragma unroll
                for (int ni = 0; ni < NI; ++ni)
                    mma_tf32(acc[mi][ni], afr[mi], bfr[ni]);
        }

        if (i + STAGES - 1 < nsteps)
            load_tile(write_stage, (i + STAGES - 1) * BK);
        asm volatile("cp.async.commit_group;\n");
        asm volatile("cp.async.wait_group %0;\n" :: "n"(STAGES - 2));
        __syncthreads();

        read_stage  = (read_stage + 1) & (STAGES - 1);
        write_stage = (write_stage + 1) & (STAGES - 1);
    }

#pragma unroll
    for (int mi = 0; mi < 4; ++mi) {
#pragma unroll
        for (int ni = 0; ni < NI; ++ni) {
            int col = nbase + wn * WNT + ni * 8 + (lane & 3) * 2;
            if (col >= N) continue;
            size_t r0 = mbase + wm * 64 + mi * 16 + (lane >> 2);
            size_t r1 = r0 + 8;
            float b0 = bias[col];
            float b1 = (col + 1 < N) ? bias[col + 1] : 0.f;
            float v0 = acc[mi][ni][0] + b0;
            float v1 = acc[mi][ni][1] + b1;
            float v2 = acc[mi][ni][2] + b0;
            float v3 = acc[mi][ni][3] + b1;
            if (relu) {
                v0 = fmaxf(v0, 0.f); v1 = fmaxf(v1, 0.f);
                v2 = fmaxf(v2, 0.f); v3 = fmaxf(v3, 0.f);
            }
            C[r0 * (size_t)N + col] = v0;
            C[r1 * (size_t)N + col] = v2;
            if (col + 1 < N) {
                C[r0 * (size_t)N + col + 1] = v1;
                C[r1 * (size_t)N + col + 1] = v3;
            }
        }
    }
}

constexpr int SMEM_128 = STAGES * (BM * SA + BK * (128 + 8)) * 4;
constexpr int SMEM_256 = STAGES * (BM * SA + BK * (256 + 8)) * 4;

// ---------------------------------------------------------------------------
// Concat W_off|W_aw
// ---------------------------------------------------------------------------
__global__ void concat_w_kernel(const float* __restrict__ W_off,
                                const float* __restrict__ b_off,
                                const float* __restrict__ W_aw,
                                const float* __restrict__ b_aw)
{
    int i = blockIdx.x * blockDim.x + threadIdx.x;
    if (i < CDIM * NOFFAW) {
        int k = i / NOFFAW, n = i % NOFFAW;
        g_Wcat[i] = (n < 64) ? W_off[k * 64 + n] : W_aw[k * 32 + (n - 64)];
    }
    if (i < NOFFAW)
        g_bcat[i] = (i < 64) ? b_off[i] : b_aw[i - 64];
}

// ---------------------------------------------------------------------------
// Bilinear sampling: 4 tokens/block, 64 threads/token, float4 per thread.
// Thread t64: h = t64>>3, l8 = t64&7 handles feature d = h*32 + l8*4 .. +3.
// ---------------------------------------------------------------------------
__global__ __launch_bounds__(256) void sample_kernel(
    const float* __restrict__ refp, float* __restrict__ attn)
{
    __shared__ float s_oa[4][NOFFAW];
    __shared__ float2 s_ref[4];

    const int tid = threadIdx.x;
    const int lt  = tid >> 6;
    const int t64 = tid & 63;
    const int h   = t64 >> 3;
    const int l8  = t64 & 7;
    const long tok0 = (long)blockIdx.x * 4;

    if (tid < 96) {
        int ltt = tid / 24, e = (tid % 24) * 4;
        *(float4*)&s_oa[ltt][e] =
            *(const float4*)(g_offaw + (tok0 + ltt) * NOFFAW + e);
    } else if (tid < 100) {
        int j = tid - 96;
        s_ref[j] = ((const float2*)refp)[tok0 + j];
    }
    __syncthreads();

    const long token = tok0 + lt;
    const int  b     = (int)(token / LQ);
    const float* oa  = s_oa[lt];
    const float rx = s_ref[lt].x, ry = s_ref[lt].y;

    // local softmax over this head's 4 logits
    float l0 = oa[64 + h * 4 + 0], l1 = oa[64 + h * 4 + 1];
    float l2 = oa[64 + h * 4 + 2], l3 = oa[64 + h * 4 + 3];
    float mx = fmaxf(fmaxf(l0, l1), fmaxf(l2, l3));
    float e0 = __expf(l0 - mx), e1 = __expf(l1 - mx);
    float e2 = __expf(l2 - mx), e3 = __expf(l3 - mx);
    float inv = 1.f / (e0 + e1 + e2 + e3);
    float aww[4] = {e0 * inv, e1 * inv, e2 * inv, e3 * inv};

    const float* vb = g_value + ((size_t)b * LQ) * CDIM + h * HD + l8 * 4;

    float4 acc = {0.f, 0.f, 0.f, 0.f};
#pragma unroll
    for (int p = 0; p < NPT; ++p) {
        float x = rx * WIMG + oa[(h * NPT + p) * 2 + 0] - 0.5f;
        float y = ry * HIMG + oa[(h * NPT + p) * 2 + 1] - 0.5f;
        float x0f = floorf(x), y0f = floorf(y);
        float fx = x - x0f, fy = y - y0f;
        int x0 = (int)x0f, y0 = (int)y0f;
        float a = aww[p];
        float w[4] = {a * (1.f - fx) * (1.f - fy), a * fx * (1.f - fy),
                      a * (1.f - fx) * fy,         a * fx * fy};
        int xs[4] = {x0, x0 + 1, x0,     x0 + 1};
        int ys[4] = {y0, y0,     y0 + 1, y0 + 1};
#pragma unroll
        for (int c = 0; c < 4; ++c) {
            int xi = xs[c], yi = ys[c];
            if (xi >= 0 && xi < WIMG && yi >= 0 && yi < HIMG && w[c] != 0.f) {
                float4 v = *(const float4*)(vb + (size_t)(yi * WIMG + xi) * CDIM);
                acc.x += v.x * w[c]; acc.y += v.y * w[c];
                acc.z += v.z * w[c]; acc.w += v.w * w[c];
            }
        }
    }
    *(float4*)(attn + (size_t)token * CDIM + h * HD + l8 * 4) = acc;
}

// ---------------------------------------------------------------------------
// Residual + LN: one warp per row, 8 floats/lane, shuffle-only reductions.
// ---------------------------------------------------------------------------
__global__ __launch_bounds__(256) void add_ln_kernel(
    const float* __restrict__ x, const float* __restrict__ y,
    const float* __restrict__ g, const float* __restrict__ be,
    float* __restrict__ out)
{
    const int lane = threadIdx.x & 31;
    const int wrp  = threadIdx.x >> 5;
    const size_t row = (size_t)blockIdx.x * 8 + wrp;
    const size_t base = row * CDIM + lane * 8;

    float4 xa = *(const float4*)(x + base);
    float4 xb = *(const float4*)(x + base + 4);
    float4 ya = *(const float4*)(y + base);
    float4 yb = *(const float4*)(y + base + 4);
    float v[8] = {xa.x + ya.x, xa.y + ya.y, xa.z + ya.z, xa.w + ya.w,
                  xb.x + yb.x, xb.y + yb.y, xb.z + yb.z, xb.w + yb.w};

    float s = 0.f;
#pragma unroll
    for (int j = 0; j < 8; ++j) s += v[j];
#pragma unroll
    for (int o = 16; o; o >>= 1) s += __shfl_xor_sync(0xffffffffu, s, o);
    float m = s * (1.0f / CDIM);

    float s2 = 0.f;
#pragma unroll
    for (int j = 0; j < 8; ++j) { float d = v[j] - m; s2 += d * d; }
#pragma unroll
    for (int o = 16; o; o >>= 1) s2 += __shfl_xor_sync(0xffffffffu, s2, o);
    float rstd = rsqrtf(s2 * (1.0f / CDIM) + 1e-5f);

    float4 ga = *(const float4*)(g + lane * 8);
    float4 gb = *(const float4*)(g + lane * 8 + 4);
    float4 ba = *(const float4*)(be + lane * 8);
    float4 bb = *(const float4*)(be + lane * 8 + 4);

    float4 oa, ob;
    oa.x = (v[0] - m) * rstd * ga.x + ba.x;
    oa.y = (v[1] - m) * rstd * ga.y + ba.y;
    oa.z = (v[2] - m) * rstd * ga.z + ba.z;
    oa.w = (v[3] - m) * rstd * ga.w + ba.w;
    ob.x = (v[4] - m) * rstd * gb.x + bb.x;
    ob.y = (v[5] - m) * rstd * gb.y + bb.y;
    ob.z = (v[6] - m) * rstd * gb.z + bb.z;
    ob.w = (v[7] - m) * rstd * gb.w + bb.w;
    *(float4*)(out + base)     = oa;
    *(float4*)(out + base + 4) = ob;
}

// ---------------------------------------------------------------------------
// Launch
// ---------------------------------------------------------------------------
extern "C" void kernel_launch(void* const* d_in, const int* in_sizes, int n_in,
                              void* d_out, int out_size)
{
    const float* query = (const float*)d_in[0];
    const float* src   = (const float*)d_in[1];
    const float* refp  = (const float*)d_in[2];
    const float* W_off = (const float*)d_in[5];
    const float* b_off = (const float*)d_in[6];
    const float* W_aw  = (const float*)d_in[7];
    const float* b_aw  = (const float*)d_in[8];
    const float* W_val = (const float*)d_in[9];
    const float* b_val = (const float*)d_in[10];
    const float* W_out = (const float*)d_in[11];
    const float* b_out = (const float*)d_in[12];
    const float* g1    = (const float*)d_in[13];
    const float* be1   = (const float*)d_in[14];
    const float* W1    = (const float*)d_in[15];
    const float* b1    = (const float*)d_in[16];
    const float* W2    = (const float*)d_in[17];
    const float* b2    = (const float*)d_in[18];
    const float* g2    = (const float*)d_in[19];
    const float* be2   = (const float*)d_in[20];
    float* out = (float*)d_out;

    float *p_value, *p_offaw, *p_attn, *p_tmp, *p_q2, *p_ffn, *p_Wcat, *p_bcat;
    cudaGetSymbolAddress((void**)&p_value, g_value);
    cudaGetSymbolAddress((void**)&p_offaw, g_offaw);
    cudaGetSymbolAddress((void**)&p_attn,  g_attn);
    cudaGetSymbolAddress((void**)&p_tmp,   g_tmp);
    cudaGetSymbolAddress((void**)&p_q2,    g_q2);
    cudaGetSymbolAddress((void**)&p_ffn,   g_ffn);
    cudaGetSymbolAddress((void**)&p_Wcat,  g_Wcat);
    cudaGetSymbolAddress((void**)&p_bcat,  g_bcat);

    cudaFuncSetAttribute(gemm_tf32_kernel<128>,
                         cudaFuncAttributeMaxDynamicSharedMemorySize, SMEM_128);
    cudaFuncSetAttribute(gemm_tf32_kernel<256>,
                         cudaFuncAttributeMaxDynamicSharedMemorySize, SMEM_256);

    const dim3 blk(256);
    const int MB = MTOK / BM;  // 625

    concat_w_kernel<<<(CDIM * NOFFAW + 255) / 256, blk>>>(W_off, b_off, W_aw, b_aw);
    gemm_tf32_kernel<256><<<dim3(CDIM / 256, MB), blk, SMEM_256>>>(src, W_val, b_val, p_value, CDIM, CDIM, 0);
    gemm_tf32_kernel<128><<<dim3(1, MB), blk, SMEM_128>>>(query, p_Wcat, p_bcat, p_offaw, NOFFAW, CDIM, 0);
    sample_kernel<<<MTOK / 4, blk>>>(refp, p_attn);
    gemm_tf32_kernel<256><<<dim3(CDIM / 256, MB), blk, SMEM_256>>>(p_attn, W_out, b_out, p_tmp, CDIM, CDIM, 0);
    add_ln_kernel<<<MTOK / 8, blk>>>(query, p_tmp, g1, be1, p_q2);
    gemm_tf32_kernel<256><<<dim3(DFF / 256, MB), blk, SMEM_256>>>(p_q2, W1, b1, p_ffn, DFF, CDIM, 1);
    gemm_tf32_kernel<256><<<dim3(CDIM / 256, MB), blk, SMEM_256>>>(p_ffn, W2, b2, p_tmp, CDIM, DFF, 0);
    add_ln_kernel<<<MTOK / 8, blk>>>(p_q2, p_tmp, g2, be2, out);
}

// round 6
// speedup vs baseline: 5.0818x; 1.4078x over previous
#include <cuda_runtime.h>
#include <cuda_fp16.h>
#include <cstdint>

#define DEV_INLINE __device__ __forceinline__

constexpr int BB   = 8;
constexpr int LQ   = 10000;
constexpr int CDIM = 256;
constexpr int NHD  = 8;
constexpr int NPT  = 4;
constexpr int DFF  = 1024;
constexpr int HIMG = 100;
constexpr int WIMG = 100;
constexpr int HD   = 32;
constexpr int MTOK = BB * LQ;  // 80000
constexpr int NOFFAW = 96;

// fp16 activations
__device__ __half g_src_h  [MTOK * CDIM];
__device__ __half g_query_h[MTOK * CDIM];
__device__ __half g_value_h[MTOK * CDIM];
__device__ __half g_attn_h [MTOK * CDIM];
__device__ __half g_q2_h   [MTOK * CDIM];
__device__ __half g_ffn_h  [MTOK * DFF];
// fp32 buffers
__device__ float g_offaw[MTOK * NOFFAW];
__device__ float g_tmp  [MTOK * CDIM];
__device__ float g_q2   [MTOK * CDIM];
// fp16 transposed weights [N][K]
__device__ __half g_WvalT[CDIM * CDIM];
__device__ __half g_WoutT[CDIM * CDIM];
__device__ __half g_W1T  [DFF * CDIM];
__device__ __half g_W2T  [CDIM * DFF];
__device__ __half g_WcatT[128 * CDIM];   // padded 96 -> 128 rows
__device__ float  g_bcat [128];

// ---------------------------------------------------------------------------
// MMA / ldmatrix helpers
// ---------------------------------------------------------------------------
DEV_INLINE void mma_f16(float* d, const uint32_t* a, const uint32_t* b) {
    asm volatile(
        "mma.sync.aligned.m16n8k16.row.col.f32.f16.f16.f32 "
        "{%0,%1,%2,%3}, {%4,%5,%6,%7}, {%8,%9}, {%0,%1,%2,%3};\n"
        : "+f"(d[0]), "+f"(d[1]), "+f"(d[2]), "+f"(d[3])
        : "r"(a[0]), "r"(a[1]), "r"(a[2]), "r"(a[3]), "r"(b[0]), "r"(b[1]));
}

DEV_INLINE void ldsm_x4(uint32_t* r, uint32_t addr) {
    asm volatile("ldmatrix.sync.aligned.m8n8.x4.shared.b16 {%0,%1,%2,%3}, [%4];"
                 : "=r"(r[0]), "=r"(r[1]), "=r"(r[2]), "=r"(r[3]) : "r"(addr));
}

DEV_INLINE void cp_async16(uint32_t dst, const void* src) {
    asm volatile("cp.async.cg.shared.global [%0], [%1], 16;\n" :: "r"(dst), "l"(src));
}

// ---------------------------------------------------------------------------
// fp16 tensor-core GEMM: C[M,N] = A[M,K] @ BT[N,K]^T + bias (+relu)
// Block 128 x BN_, BK=32; 8 warps (64 x BN_/4 each); 4-stage cp.async.
// smem rows are 64B (32 halves); chunk swizzle c ^ ((row>>1)&3).
// OUT_H: 0 -> float output, 1 -> half output.
// ---------------------------------------------------------------------------
constexpr int BM = 128, BK = 32;
constexpr int STAGES = 4;

template<int BN_, int OUT_H>
__global__ __launch_bounds__(256) void gemm_h_kernel(
    const __half* __restrict__ A, const __half* __restrict__ BT,
    const float* __restrict__ bias, void* __restrict__ Cv,
    int N, int K, int relu)
{
    constexpr int WNT = BN_ / 4;          // warp n-tile (64 or 32)
    constexpr int NI  = WNT / 8;          // 8 or 4 n-subtiles
    constexpr int A_BYTES = BM * 64;      // 8192
    constexpr int B_BYTES = BN_ * 64;
    constexpr int STAGE_BYTES = A_BYTES + B_BYTES;

    extern __shared__ char dsm[];
    uint32_t sm0 = (uint32_t)__cvta_generic_to_shared(dsm);

    const int tid  = threadIdx.x;
    const int lane = tid & 31;
    const int wid  = tid >> 5;
    const int wm   = wid >> 2;            // 0..1
    const int wn   = wid & 3;             // 0..3
    const size_t mbase = (size_t)blockIdx.y * BM;
    const int    nbase = blockIdx.x * BN_;

    const int g  = lane >> 3;             // ldmatrix group 0..3
    const int rr = lane & 7;

    // A fragment addressing: row = rA0 + rr + (g&1)*8 + mi*16, kchunk += g>>1
    const int rowA = wm * 64 + rr + (g & 1) * 8;
    const uint32_t swA = (uint32_t)((rowA >> 1) & 3);
    const uint32_t aoff[2] = { (((0u + (g >> 1)) ^ swA) << 4),
                               (((2u + (g >> 1)) ^ swA) << 4) };
    const uint32_t aBase = (uint32_t)rowA * 64u;

    // B fragment addressing: row = n0 + rr + (g>>1)*8 + p*16, kchunk += g&1
    const int rowB = wn * WNT + rr + (g >> 1) * 8;
    const uint32_t swB = (uint32_t)((rowB >> 1) & 3);
    const uint32_t boff[2] = { (((0u + (g & 1)) ^ swB) << 4),
                               (((2u + (g & 1)) ^ swB) << 4) };
    const uint32_t bBase = (uint32_t)rowB * 64u;

    // cp.async addressing (16B = 8 halves per chunk, 4 chunks per 64B row)
    const int arow = tid >> 1;                 // 0..127
    const int ac   = tid & 1;                  // chunks 0-1 / 2-3 split
    const __half* Ab = A + mbase * (size_t)K;

    float acc[4][NI][4];
#pragma unroll
    for (int mi = 0; mi < 4; ++mi)
#pragma unroll
        for (int ni = 0; ni < NI; ++ni)
#pragma unroll
            for (int j = 0; j < 4; ++j) acc[mi][ni][j] = 0.f;

    auto load_tile = [&](int stage, int k0) {
        uint32_t sA = sm0 + stage * STAGE_BYTES;
        uint32_t sB = sA + A_BYTES;
        // A: 128 rows x 4 chunks = 512 chunks, 256 threads -> 2 each
#pragma unroll
        for (int i = 0; i < 2; ++i) {
            int c = ac * 2 + i;
            cp_async16(sA + arow * 64 + ((c ^ ((arow >> 1) & 3)) << 4),
                       Ab + (size_t)arow * K + k0 + c * 8);
        }
        // B: BN_ rows x 4 chunks
#pragma unroll
        for (int it = 0; it < BN_ / 64; ++it) {
            int idx = tid + it * 256;
            int row = idx >> 2, c = idx & 3;
            cp_async16(sB + row * 64 + ((c ^ ((row >> 1) & 3)) << 4),
                       BT + (size_t)(nbase + row) * K + k0 + c * 8);
        }
    };

    const int ntiles = K / BK;

#pragma unroll
    for (int s = 0; s < STAGES - 1; ++s) {
        if (s < ntiles) load_tile(s, s * BK);
        asm volatile("cp.async.commit_group;\n");
    }
    asm volatile("cp.async.wait_group %0;\n" :: "n"(STAGES - 2));
    __syncthreads();

    int read_stage = 0, write_stage = STAGES - 1;

    for (int i = 0; i < ntiles; ++i) {
        uint32_t sA = sm0 + read_stage * STAGE_BYTES;
        uint32_t sB = sA + A_BYTES;

#pragma unroll
        for (int ks = 0; ks < 2; ++ks) {
            uint32_t afr[4][4], bfr[NI / 2][4];
#pragma unroll
            for (int mi = 0; mi < 4; ++mi)
                ldsm_x4(afr[mi], sA + aBase + mi * 1024 + aoff[ks]);
#pragma unroll
            for (int p = 0; p < NI / 2; ++p)
                ldsm_x4(bfr[p], sB + bBase + p * 1024 + boff[ks]);
#pragma unroll
            for (int mi = 0; mi < 4; ++mi)
#pragma unroll
                for (int ni = 0; ni < NI; ++ni)
                    mma_f16(acc[mi][ni], afr[mi], &bfr[ni >> 1][(ni & 1) * 2]);
        }

        if (i + STAGES - 1 < ntiles)
            load_tile(write_stage, (i + STAGES - 1) * BK);
        asm volatile("cp.async.commit_group;\n");
        asm volatile("cp.async.wait_group %0;\n" :: "n"(STAGES - 2));
        __syncthreads();

        read_stage  = (read_stage + 1) & (STAGES - 1);
        write_stage = (write_stage + 1) & (STAGES - 1);
    }

    // ---- epilogue ----
#pragma unroll
    for (int mi = 0; mi < 4; ++mi) {
#pragma unroll
        for (int ni = 0; ni < NI; ++ni) {
            int col = nbase + wn * WNT + ni * 8 + (lane & 3) * 2;
            if (col >= N) continue;
            size_t r0 = mbase + wm * 64 + mi * 16 + (lane >> 2);
            size_t r1 = r0 + 8;
            float b0 = bias[col];
            float b1 = bias[col + 1];
            float v0 = acc[mi][ni][0] + b0;
            float v1 = acc[mi][ni][1] + b1;
            float v2 = acc[mi][ni][2] + b0;
            float v3 = acc[mi][ni][3] + b1;
            if (relu) {
                v0 = fmaxf(v0, 0.f); v1 = fmaxf(v1, 0.f);
                v2 = fmaxf(v2, 0.f); v3 = fmaxf(v3, 0.f);
            }
            if (OUT_H) {
                __half* C = (__half*)Cv;
                *(__half2*)(C + r0 * (size_t)N + col) = __floats2half2_rn(v0, v1);
                *(__half2*)(C + r1 * (size_t)N + col) = __floats2half2_rn(v2, v3);
            } else {
                float* C = (float*)Cv;
                C[r0 * (size_t)N + col]     = v0;
                C[r0 * (size_t)N + col + 1] = v1;
                C[r1 * (size_t)N + col]     = v2;
                C[r1 * (size_t)N + col + 1] = v3;
            }
        }
    }
}

constexpr int SMEM_G256 = STAGES * (BM * 64 + 256 * 64);  // 98304
constexpr int SMEM_G128 = STAGES * (BM * 64 + 128 * 64);  // 65536

// ---------------------------------------------------------------------------
// fp32 -> fp16 conversion
// ---------------------------------------------------------------------------
__global__ void f2h_kernel(const float* __restrict__ in, __half* __restrict__ out,
                           long n)
{
    long i = ((long)blockIdx.x * blockDim.x + threadIdx.x) * 4;
    if (i < n) {
        float4 v = *(const float4*)(in + i);
        __half2 h0 = __floats2half2_rn(v.x, v.y);
        __half2 h1 = __floats2half2_rn(v.z, v.w);
        *(__half2*)(out + i)     = h0;
        *(__half2*)(out + i + 2) = h1;
    }
}

// ---------------------------------------------------------------------------
// Weight transpose + convert: in fp32 [K,N] -> out fp16 [N,K]
// ---------------------------------------------------------------------------
__global__ void transpose_h_kernel(const float* __restrict__ in,
                                   __half* __restrict__ out, int K, int N)
{
    __shared__ float t[32][33];
    int k0 = blockIdx.y * 32, n0 = blockIdx.x * 32;
    int x = threadIdx.x, y = threadIdx.y;
#pragma unroll
    for (int i = y; i < 32; i += 8)
        t[i][x] = in[(size_t)(k0 + i) * N + n0 + x];
    __syncthreads();
#pragma unroll
    for (int i = y; i < 32; i += 8)
        out[(size_t)(n0 + i) * K + k0 + x] = __float2half(t[x][i]);
}

// Build padded transposed concat weights (rows 96..127 zero) + bias
__global__ void concat_t_kernel(const float* __restrict__ W_off,
                                const float* __restrict__ b_off,
                                const float* __restrict__ W_aw,
                                const float* __restrict__ b_aw)
{
    int i = blockIdx.x * blockDim.x + threadIdx.x;
    if (i < 128 * CDIM) {
        int n = i / CDIM, k = i % CDIM;
        float v = 0.f;
        if (n < 64)       v = W_off[k * 64 + n];
        else if (n < 96)  v = W_aw[k * 32 + (n - 64)];
        g_WcatT[i] = __float2half(v);
    }
    if (i < 128)
        g_bcat[i] = (i < 64) ? b_off[i] : (i < 96 ? b_aw[i - 64] : 0.f);
}

// ---------------------------------------------------------------------------
// Bilinear sampling (4 tokens/block, 64 threads/token), fp16 value -> fp16 attn
// ---------------------------------------------------------------------------
__global__ __launch_bounds__(256) void sample_kernel(
    const float* __restrict__ refp, __half* __restrict__ attn)
{
    __shared__ float s_oa[4][NOFFAW];
    __shared__ float2 s_ref[4];

    const int tid = threadIdx.x;
    const int lt  = tid >> 6;
    const int t64 = tid & 63;
    const int h   = t64 >> 3;
    const int l8  = t64 & 7;
    const long tok0 = (long)blockIdx.x * 4;

    if (tid < 96) {
        int ltt = tid / 24, e = (tid % 24) * 4;
        *(float4*)&s_oa[ltt][e] =
            *(const float4*)(g_offaw + (tok0 + ltt) * NOFFAW + e);
    } else if (tid < 100) {
        int j = tid - 96;
        s_ref[j] = ((const float2*)refp)[tok0 + j];
    }
    __syncthreads();

    const long token = tok0 + lt;
    const int  b     = (int)(token / LQ);
    const float* oa  = s_oa[lt];
    const float rx = s_ref[lt].x, ry = s_ref[lt].y;

    float l0 = oa[64 + h * 4 + 0], l1 = oa[64 + h * 4 + 1];
    float l2 = oa[64 + h * 4 + 2], l3 = oa[64 + h * 4 + 3];
    float mx = fmaxf(fmaxf(l0, l1), fmaxf(l2, l3));
    float e0 = __expf(l0 - mx), e1 = __expf(l1 - mx);
    float e2 = __expf(l2 - mx), e3 = __expf(l3 - mx);
    float inv = 1.f / (e0 + e1 + e2 + e3);
    float aww[4] = {e0 * inv, e1 * inv, e2 * inv, e3 * inv};

    const __half* vb = g_value_h + ((size_t)b * LQ) * CDIM + h * HD + l8 * 4;

    float4 acc = {0.f, 0.f, 0.f, 0.f};
#pragma unroll
    for (int p = 0; p < NPT; ++p) {
        float x = rx * WIMG + oa[(h * NPT + p) * 2 + 0] - 0.5f;
        float y = ry * HIMG + oa[(h * NPT + p) * 2 + 1] - 0.5f;
        float x0f = floorf(x), y0f = floorf(y);
        float fx = x - x0f, fy = y - y0f;
        int x0 = (int)x0f, y0 = (int)y0f;
        float a = aww[p];
        float w[4] = {a * (1.f - fx) * (1.f - fy), a * fx * (1.f - fy),
                      a * (1.f - fx) * fy,         a * fx * fy};
        int xs[4] = {x0, x0 + 1, x0,     x0 + 1};
        int ys[4] = {y0, y0,     y0 + 1, y0 + 1};
#pragma unroll
        for (int c = 0; c < 4; ++c) {
            int xi = xs[c], yi = ys[c];
            if (xi >= 0 && xi < WIMG && yi >= 0 && yi < HIMG && w[c] != 0.f) {
                const __half2* vp =
                    (const __half2*)(vb + (size_t)(yi * WIMG + xi) * CDIM);
                float2 u0 = __half22float2(vp[0]);
                float2 u1 = __half22float2(vp[1]);
                acc.x += u0.x * w[c]; acc.y += u0.y * w[c];
                acc.z += u1.x * w[c]; acc.w += u1.y * w[c];
            }
        }
    }
    __half* dst = attn + (size_t)token * CDIM + h * HD + l8 * 4;
    *(__half2*)(dst)     = __floats2half2_rn(acc.x, acc.y);
    *(__half2*)(dst + 2) = __floats2half2_rn(acc.z, acc.w);
}

// ---------------------------------------------------------------------------
// Residual + LN; optional fp16 twin output
// ---------------------------------------------------------------------------
__global__ __launch_bounds__(256) void add_ln_kernel(
    const float* __restrict__ x, const float* __restrict__ y,
    const float* __restrict__ g, const float* __restrict__ be,
    float* __restrict__ out, __half* __restrict__ hout)
{
    const int lane = threadIdx.x & 31;
    const int wrp  = threadIdx.x >> 5;
    const size_t row = (size_t)blockIdx.x * 8 + wrp;
    const size_t base = row * CDIM + lane * 8;

    float4 xa = *(const float4*)(x + base);
    float4 xb = *(const float4*)(x + base + 4);
    float4 ya = *(const float4*)(y + base);
    float4 yb = *(const float4*)(y + base + 4);
    float v[8] = {xa.x + ya.x, xa.y + ya.y, xa.z + ya.z, xa.w + ya.w,
                  xb.x + yb.x, xb.y + yb.y, xb.z + yb.z, xb.w + yb.w};

    float s = 0.f;
#pragma unroll
    for (int j = 0; j < 8; ++j) s += v[j];
#pragma unroll
    for (int o = 16; o; o >>= 1) s += __shfl_xor_sync(0xffffffffu, s, o);
    float m = s * (1.0f / CDIM);

    float s2 = 0.f;
#pragma unroll
    for (int j = 0; j < 8; ++j) { float d = v[j] - m; s2 += d * d; }
#pragma unroll
    for (int o = 16; o; o >>= 1) s2 += __shfl_xor_sync(0xffffffffu, s2, o);
    float rstd = rsqrtf(s2 * (1.0f / CDIM) + 1e-5f);

    float4 ga = *(const float4*)(g + lane * 8);
    float4 gb = *(const float4*)(g + lane * 8 + 4);
    float4 ba = *(const float4*)(be + lane * 8);
    float4 bb = *(const float4*)(be + lane * 8 + 4);

    float o0 = (v[0] - m) * rstd * ga.x + ba.x;
    float o1 = (v[1] - m) * rstd * ga.y + ba.y;
    float o2 = (v[2] - m) * rstd * ga.z + ba.z;
    float o3 = (v[3] - m) * rstd * ga.w + ba.w;
    float o4 = (v[4] - m) * rstd * gb.x + bb.x;
    float o5 = (v[5] - m) * rstd * gb.y + bb.y;
    float o6 = (v[6] - m) * rstd * gb.z + bb.z;
    float o7 = (v[7] - m) * rstd * gb.w + bb.w;

    *(float4*)(out + base)     = make_float4(o0, o1, o2, o3);
    *(float4*)(out + base + 4) = make_float4(o4, o5, o6, o7);
    if (hout) {
        *(__half2*)(hout + base)     = __floats2half2_rn(o0, o1);
        *(__half2*)(hout + base + 2) = __floats2half2_rn(o2, o3);
        *(__half2*)(hout + base + 4) = __floats2half2_rn(o4, o5);
        *(__half2*)(hout + base + 6) = __floats2half2_rn(o6, o7);
    }
}

// ---------------------------------------------------------------------------
// Launch
// ---------------------------------------------------------------------------
extern "C" void kernel_launch(void* const* d_in, const int* in_sizes, int n_in,
                              void* d_out, int out_size)
{
    const float* query = (const float*)d_in[0];
    const float* src   = (const float*)d_in[1];
    const float* refp  = (const float*)d_in[2];
    const float* W_off = (const float*)d_in[5];
    const float* b_off = (const float*)d_in[6];
    const float* W_aw  = (const float*)d_in[7];
    const float* b_aw  = (const float*)d_in[8];
    const float* W_val = (const float*)d_in[9];
    const float* b_val = (const float*)d_in[10];
    const float* W_out = (const float*)d_in[11];
    const float* b_out = (const float*)d_in[12];
    const float* g1    = (const float*)d_in[13];
    const float* be1   = (const float*)d_in[14];
    const float* W1    = (const float*)d_in[15];
    const float* b1    = (const float*)d_in[16];
    const float* W2    = (const float*)d_in[17];
    const float* b2    = (const float*)d_in[18];
    const float* g2    = (const float*)d_in[19];
    const float* be2   = (const float*)d_in[20];
    float* out = (float*)d_out;

    __half *p_src_h, *p_query_h, *p_value_h, *p_attn_h, *p_q2_h, *p_ffn_h;
    __half *p_WvalT, *p_WoutT, *p_W1T, *p_W2T, *p_WcatT;
    float *p_offaw, *p_tmp, *p_q2, *p_bcat;
    cudaGetSymbolAddress((void**)&p_src_h,   g_src_h);
    cudaGetSymbolAddress((void**)&p_query_h, g_query_h);
    cudaGetSymbolAddress((void**)&p_value_h, g_value_h);
    cudaGetSymbolAddress((void**)&p_attn_h,  g_attn_h);
    cudaGetSymbolAddress((void**)&p_q2_h,    g_q2_h);
    cudaGetSymbolAddress((void**)&p_ffn_h,   g_ffn_h);
    cudaGetSymbolAddress((void**)&p_offaw,   g_offaw);
    cudaGetSymbolAddress((void**)&p_tmp,     g_tmp);
    cudaGetSymbolAddress((void**)&p_q2,      g_q2);
    cudaGetSymbolAddress((void**)&p_WvalT,   g_WvalT);
    cudaGetSymbolAddress((void**)&p_WoutT,   g_WoutT);
    cudaGetSymbolAddress((void**)&p_W1T,     g_W1T);
    cudaGetSymbolAddress((void**)&p_W2T,     g_W2T);
    cudaGetSymbolAddress((void**)&p_WcatT,   g_WcatT);
    cudaGetSymbolAddress((void**)&p_bcat,    g_bcat);

    cudaFuncSetAttribute(gemm_h_kernel<256, 0>,
                         cudaFuncAttributeMaxDynamicSharedMemorySize, SMEM_G256);
    cudaFuncSetAttribute(gemm_h_kernel<256, 1>,
                         cudaFuncAttributeMaxDynamicSharedMemorySize, SMEM_G256);
    cudaFuncSetAttribute(gemm_h_kernel<128, 0>,
                         cudaFuncAttributeMaxDynamicSharedMemorySize, SMEM_G128);

    const int MB = MTOK / BM;  // 625
    dim3 tb(32, 8);
    const long NELT = (long)MTOK * CDIM;

    // prep: conversions + weight transposes
    f2h_kernel<<<(int)((NELT / 4 + 255) / 256), 256>>>(src,   p_src_h,   NELT);
    f2h_kernel<<<(int)((NELT / 4 + 255) / 256), 256>>>(query, p_query_h, NELT);
    transpose_h_kernel<<<dim3(CDIM / 32, CDIM / 32), tb>>>(W_val, p_WvalT, CDIM, CDIM);
    transpose_h_kernel<<<dim3(CDIM / 32, CDIM / 32), tb>>>(W_out, p_WoutT, CDIM, CDIM);
    transpose_h_kernel<<<dim3(DFF / 32,  CDIM / 32), tb>>>(W1,    p_W1T,   CDIM, DFF);
    transpose_h_kernel<<<dim3(CDIM / 32, DFF / 32),  tb>>>(W2,    p_W2T,   DFF,  CDIM);
    concat_t_kernel<<<(128 * CDIM + 255) / 256, 256>>>(W_off, b_off, W_aw, b_aw);

    // main pipeline
    gemm_h_kernel<256, 1><<<dim3(1, MB), 256, SMEM_G256>>>(
        p_src_h, p_WvalT, b_val, p_value_h, CDIM, CDIM, 0);
    gemm_h_kernel<128, 0><<<dim3(1, MB), 256, SMEM_G128>>>(
        p_query_h, p_WcatT, p_bcat, p_offaw, NOFFAW, CDIM, 0);
    sample_kernel<<<MTOK / 4, 256>>>(refp, p_attn_h);
    gemm_h_kernel<256, 0><<<dim3(1, MB), 256, SMEM_G256>>>(
        p_attn_h, p_WoutT, b_out, p_tmp, CDIM, CDIM, 0);
    add_ln_kernel<<<MTOK / 8, 256>>>(query, p_tmp, g1, be1, p_q2, p_q2_h);
    gemm_h_kernel<256, 1><<<dim3(DFF / 256, MB), 256, SMEM_G256>>>(
        p_q2_h, p_W1T, b1, p_ffn_h, DFF, CDIM, 1);
    gemm_h_kernel<256, 0><<<dim3(1, MB), 256, SMEM_G256>>>(
        p_ffn_h, p_W2T, b2, p_tmp, CDIM, DFF, 0);
    add_ln_kernel<<<MTOK / 8, 256>>>(p_q2, p_tmp, g2, be2, out, nullptr);
}

// round 7
// speedup vs baseline: 5.4960x; 1.0815x over previous
#include <cuda_runtime.h>
#include <cuda_fp16.h>
#include <cstdint>

#define DEV_INLINE __device__ __forceinline__

constexpr int BB   = 8;
constexpr int LQ   = 10000;
constexpr int CDIM = 256;
constexpr int NHD  = 8;
constexpr int NPT  = 4;
constexpr int DFF  = 1024;
constexpr int HIMG = 100;
constexpr int WIMG = 100;
constexpr int HD   = 32;
constexpr int MTOK = BB * LQ;  // 80000
constexpr int NOFFAW = 96;

// fp16 activations
__device__ __half g_src_h  [MTOK * CDIM];
__device__ __half g_query_h[MTOK * CDIM];
__device__ __half g_value_h[MTOK * CDIM];
__device__ __half g_attn_h [MTOK * CDIM];
__device__ __half g_q2_h   [MTOK * CDIM];
__device__ __half g_ffn_h  [MTOK * DFF];
// fp32 buffers
__device__ float g_offaw[MTOK * NOFFAW];
__device__ float g_q2   [MTOK * CDIM];
// fp16 transposed weights [N][K]
__device__ __half g_WvalT[CDIM * CDIM];
__device__ __half g_WoutT[CDIM * CDIM];
__device__ __half g_W1T  [DFF * CDIM];
__device__ __half g_W2T  [CDIM * DFF];
__device__ __half g_WcatT[128 * CDIM];   // padded 96 -> 128 rows
__device__ float  g_bcat [128];

// ---------------------------------------------------------------------------
// MMA / ldmatrix helpers
// ---------------------------------------------------------------------------
DEV_INLINE void mma_f16(float* d, const uint32_t* a, const uint32_t* b) {
    asm volatile(
        "mma.sync.aligned.m16n8k16.row.col.f32.f16.f16.f32 "
        "{%0,%1,%2,%3}, {%4,%5,%6,%7}, {%8,%9}, {%0,%1,%2,%3};\n"
        : "+f"(d[0]), "+f"(d[1]), "+f"(d[2]), "+f"(d[3])
        : "r"(a[0]), "r"(a[1]), "r"(a[2]), "r"(a[3]), "r"(b[0]), "r"(b[1]));
}

DEV_INLINE void ldsm_x4(uint32_t* r, uint32_t addr) {
    asm volatile("ldmatrix.sync.aligned.m8n8.x4.shared.b16 {%0,%1,%2,%3}, [%4];"
                 : "=r"(r[0]), "=r"(r[1]), "=r"(r[2]), "=r"(r[3]) : "r"(addr));
}

DEV_INLINE void cp_async16(uint32_t dst, const void* src) {
    asm volatile("cp.async.cg.shared.global [%0], [%1], 16;\n" :: "r"(dst), "l"(src));
}

// ---------------------------------------------------------------------------
// fp16 tensor-core GEMM: acc = A[M,K] @ BT[N,K]^T
// Block 128 x BN_, BK=32; 8 warps; 4-stage cp.async; swizzled 64B smem rows.
// MODE 0: f32 out (bias,+relu)   MODE 1: fp16 out (bias,+relu)
// MODE 2: fused residual + LayerNorm (grid.x==1, BN_==N==256):
//         out32 = LN(acc + bias + resid), optional fp16 twin out16.
// ---------------------------------------------------------------------------
constexpr int BM = 128, BK = 32;
constexpr int STAGES = 4;

template<int BN_, int MODE>
__global__ __launch_bounds__(256) void gemm_h_kernel(
    const __half* __restrict__ A, const __half* __restrict__ BT,
    const float* __restrict__ bias, void* __restrict__ Cv,
    int N, int K, int relu,
    const float* __restrict__ resid, const float* __restrict__ gam,
    const float* __restrict__ bet, __half* __restrict__ out16)
{
    constexpr int WNT = BN_ / 4;          // warp n-tile (64 or 32)
    constexpr int NI  = WNT / 8;          // 8 or 4 n-subtiles
    constexpr int A_BYTES = BM * 64;      // 8192
    constexpr int B_BYTES = BN_ * 64;
    constexpr int STAGE_BYTES = A_BYTES + B_BYTES;

    extern __shared__ char dsm[];
    uint32_t sm0 = (uint32_t)__cvta_generic_to_shared(dsm);

    __shared__ float s_bias[BN_];
    __shared__ float s_red[128][8];   // [row][wn*2 + {sum,sq}] (MODE 2)
    __shared__ float s_g[256], s_b[256];

    const int tid  = threadIdx.x;
    const int lane = tid & 31;
    const int wid  = tid >> 5;
    const int wm   = wid >> 2;            // 0..1
    const int wn   = wid & 3;             // 0..3
    const size_t mbase = (size_t)blockIdx.y * BM;
    const int    nbase = blockIdx.x * BN_;

    const int g  = lane >> 3;             // ldmatrix group 0..3
    const int rr = lane & 7;

    const int rowA = wm * 64 + rr + (g & 1) * 8;
    const uint32_t swA = (uint32_t)((rowA >> 1) & 3);
    const uint32_t aoff[2] = { (((0u + (g >> 1)) ^ swA) << 4),
                               (((2u + (g >> 1)) ^ swA) << 4) };
    const uint32_t aBase = (uint32_t)rowA * 64u;

    const int rowB = wn * WNT + rr + (g >> 1) * 8;
    const uint32_t swB = (uint32_t)((rowB >> 1) & 3);
    const uint32_t boff[2] = { (((0u + (g & 1)) ^ swB) << 4),
                               (((2u + (g & 1)) ^ swB) << 4) };
    const uint32_t bBase = (uint32_t)rowB * 64u;

    const int arow = tid >> 1;
    const int ac   = tid & 1;
    const __half* Ab = A + mbase * (size_t)K;

    for (int c = tid; c < BN_; c += 256) s_bias[c] = bias[nbase + c];

    float acc[4][NI][4];
#pragma unroll
    for (int mi = 0; mi < 4; ++mi)
#pragma unroll
        for (int ni = 0; ni < NI; ++ni)
#pragma unroll
            for (int j = 0; j < 4; ++j) acc[mi][ni][j] = 0.f;

    auto load_tile = [&](int stage, int k0) {
        uint32_t sA = sm0 + stage * STAGE_BYTES;
        uint32_t sB = sA + A_BYTES;
#pragma unroll
        for (int i = 0; i < 2; ++i) {
            int c = ac * 2 + i;
            cp_async16(sA + arow * 64 + ((c ^ ((arow >> 1) & 3)) << 4),
                       Ab + (size_t)arow * K + k0 + c * 8);
        }
#pragma unroll
        for (int it = 0; it < BN_ / 64; ++it) {
            int idx = tid + it * 256;
            int row = idx >> 2, c = idx & 3;
            cp_async16(sB + row * 64 + ((c ^ ((row >> 1) & 3)) << 4),
                       BT + (size_t)(nbase + row) * K + k0 + c * 8);
        }
    };

    const int ntiles = K / BK;

#pragma unroll
    for (int s = 0; s < STAGES - 1; ++s) {
        if (s < ntiles) load_tile(s, s * BK);
        asm volatile("cp.async.commit_group;\n");
    }
    asm volatile("cp.async.wait_group %0;\n" :: "n"(STAGES - 2));
    __syncthreads();

    int read_stage = 0, write_stage = STAGES - 1;

    for (int i = 0; i < ntiles; ++i) {
        uint32_t sA = sm0 + read_stage * STAGE_BYTES;
        uint32_t sB = sA + A_BYTES;

#pragma unroll
        for (int ks = 0; ks < 2; ++ks) {
            uint32_t afr[4][4], bfr[NI / 2][4];
#pragma unroll
            for (int mi = 0; mi < 4; ++mi)
                ldsm_x4(afr[mi], sA + aBase + mi * 1024 + aoff[ks]);
#pragma unroll
            for (int p = 0; p < NI / 2; ++p)
                ldsm_x4(bfr[p], sB + bBase + p * 1024 + boff[ks]);
#pragma unroll
            for (int mi = 0; mi < 4; ++mi)
#pragma unroll
                for (int ni = 0; ni < NI; ++ni)
                    mma_f16(acc[mi][ni], afr[mi], &bfr[ni >> 1][(ni & 1) * 2]);
        }

        if (i + STAGES - 1 < ntiles)
            load_tile(write_stage, (i + STAGES - 1) * BK);
        asm volatile("cp.async.commit_group;\n");
        asm volatile("cp.async.wait_group %0;\n" :: "n"(STAGES - 2));
        __syncthreads();

        read_stage  = (read_stage + 1) & (STAGES - 1);
        write_stage = (write_stage + 1) & (STAGES - 1);
    }

    if (MODE == 2) {
        // ---- fused residual + LayerNorm epilogue (nbase==0, N==256) ----
#pragma unroll
        for (int mi = 0; mi < 4; ++mi) {
            float psum0 = 0.f, psq0 = 0.f, psum1 = 0.f, psq1 = 0.f;
            size_t r0 = mbase + wm * 64 + mi * 16 + (lane >> 2);
            size_t r1 = r0 + 8;
#pragma unroll
            for (int ni = 0; ni < NI; ++ni) {
                int col = wn * WNT + ni * 8 + (lane & 3) * 2;
                float b0 = s_bias[col], b1 = s_bias[col + 1];
                float2 x0 = *(const float2*)(resid + r0 * 256 + col);
                float2 x1 = *(const float2*)(resid + r1 * 256 + col);
                float v0 = acc[mi][ni][0] + b0 + x0.x;
                float v1 = acc[mi][ni][1] + b1 + x0.y;
                float v2 = acc[mi][ni][2] + b0 + x1.x;
                float v3 = acc[mi][ni][3] + b1 + x1.y;
                acc[mi][ni][0] = v0; acc[mi][ni][1] = v1;
                acc[mi][ni][2] = v2; acc[mi][ni][3] = v3;
                psum0 += v0 + v1; psq0 += v0 * v0 + v1 * v1;
                psum1 += v2 + v3; psq1 += v2 * v2 + v3 * v3;
            }
#pragma unroll
            for (int o = 1; o <= 2; o <<= 1) {
                psum0 += __shfl_xor_sync(0xffffffffu, psum0, o);
                psq0  += __shfl_xor_sync(0xffffffffu, psq0,  o);
                psum1 += __shfl_xor_sync(0xffffffffu, psum1, o);
                psq1  += __shfl_xor_sync(0xffffffffu, psq1,  o);
            }
            if ((lane & 3) == 0) {
                int rl = wm * 64 + mi * 16 + (lane >> 2);
                s_red[rl][wn * 2] = psum0;     s_red[rl][wn * 2 + 1] = psq0;
                s_red[rl + 8][wn * 2] = psum1; s_red[rl + 8][wn * 2 + 1] = psq1;
            }
        }
        s_g[tid] = gam[tid];
        s_b[tid] = bet[tid];
        __syncthreads();

        float mstat[4][2][2];
#pragma unroll
        for (int mi = 0; mi < 4; ++mi) {
#pragma unroll
            for (int hh = 0; hh < 2; ++hh) {
                int rl = wm * 64 + mi * 16 + (lane >> 2) + hh * 8;
                float su = s_red[rl][0] + s_red[rl][2] + s_red[rl][4] + s_red[rl][6];
                float sq = s_red[rl][1] + s_red[rl][3] + s_red[rl][5] + s_red[rl][7];
                float m = su * (1.0f / 256);
                mstat[mi][hh][0] = m;
                mstat[mi][hh][1] = rsqrtf(sq * (1.0f / 256) - m * m + 1e-5f);
            }
        }

        float* C = (float*)Cv;
#pragma unroll
        for (int mi = 0; mi < 4; ++mi) {
            size_t r0 = mbase + wm * 64 + mi * 16 + (lane >> 2);
            size_t r1 = r0 + 8;
            float m0 = mstat[mi][0][0], s0 = mstat[mi][0][1];
            float m1 = mstat[mi][1][0], s1 = mstat[mi][1][1];
#pragma unroll
            for (int ni = 0; ni < NI; ++ni) {
                int col = wn * WNT + ni * 8 + (lane & 3) * 2;
                float g0 = s_g[col], g1v = s_g[col + 1];
                float be0 = s_b[col], be1 = s_b[col + 1];
                float o0 = (acc[mi][ni][0] - m0) * s0 * g0  + be0;
                float o1 = (acc[mi][ni][1] - m0) * s0 * g1v + be1;
                float o2 = (acc[mi][ni][2] - m1) * s1 * g0  + be0;
                float o3 = (acc[mi][ni][3] - m1) * s1 * g1v + be1;
                *(float2*)(C + r0 * 256 + col) = make_float2(o0, o1);
                *(float2*)(C + r1 * 256 + col) = make_float2(o2, o3);
                if (out16) {
                    *(__half2*)(out16 + r0 * 256 + col) = __floats2half2_rn(o0, o1);
                    *(__half2*)(out16 + r1 * 256 + col) = __floats2half2_rn(o2, o3);
                }
            }
        }
        return;
    }

    // ---- plain epilogue (MODE 0/1) ----
#pragma unroll
    for (int mi = 0; mi < 4; ++mi) {
#pragma unroll
        for (int ni = 0; ni < NI; ++ni) {
            int col = nbase + wn * WNT + ni * 8 + (lane & 3) * 2;
            if (col >= N) continue;
            size_t r0 = mbase + wm * 64 + mi * 16 + (lane >> 2);
            size_t r1 = r0 + 8;
            float b0 = s_bias[col - nbase];
            float b1 = s_bias[col - nbase + 1];
            float v0 = acc[mi][ni][0] + b0;
            float v1 = acc[mi][ni][1] + b1;
            float v2 = acc[mi][ni][2] + b0;
            float v3 = acc[mi][ni][3] + b1;
            if (relu) {
                v0 = fmaxf(v0, 0.f); v1 = fmaxf(v1, 0.f);
                v2 = fmaxf(v2, 0.f); v3 = fmaxf(v3, 0.f);
            }
            if (MODE == 1) {
                __half* C = (__half*)Cv;
                *(__half2*)(C + r0 * (size_t)N + col) = __floats2half2_rn(v0, v1);
                *(__half2*)(C + r1 * (size_t)N + col) = __floats2half2_rn(v2, v3);
            } else {
                float* C = (float*)Cv;
                C[r0 * (size_t)N + col]     = v0;
                C[r0 * (size_t)N + col + 1] = v1;
                C[r1 * (size_t)N + col]     = v2;
                C[r1 * (size_t)N + col + 1] = v3;
            }
        }
    }
}

constexpr int SMEM_G256 = STAGES * (BM * 64 + 256 * 64);  // 98304
constexpr int SMEM_G128 = STAGES * (BM * 64 + 128 * 64);  // 65536

// ---------------------------------------------------------------------------
// fp32 -> fp16 conversion
// ---------------------------------------------------------------------------
__global__ void f2h_kernel(const float* __restrict__ in, __half* __restrict__ out,
                           long n)
{
    long i = ((long)blockIdx.x * blockDim.x + threadIdx.x) * 4;
    if (i < n) {
        float4 v = *(const float4*)(in + i);
        *(__half2*)(out + i)     = __floats2half2_rn(v.x, v.y);
        *(__half2*)(out + i + 2) = __floats2half2_rn(v.z, v.w);
    }
}

// ---------------------------------------------------------------------------
// Weight transpose + convert: fp32 [K,N] -> fp16 [N,K]
// ---------------------------------------------------------------------------
__global__ void transpose_h_kernel(const float* __restrict__ in,
                                   __half* __restrict__ out, int K, int N)
{
    __shared__ float t[32][33];
    int k0 = blockIdx.y * 32, n0 = blockIdx.x * 32;
    int x = threadIdx.x, y = threadIdx.y;
#pragma unroll
    for (int i = y; i < 32; i += 8)
        t[i][x] = in[(size_t)(k0 + i) * N + n0 + x];
    __syncthreads();
#pragma unroll
    for (int i = y; i < 32; i += 8)
        out[(size_t)(n0 + i) * K + k0 + x] = __float2half(t[x][i]);
}

__global__ void concat_t_kernel(const float* __restrict__ W_off,
                                const float* __restrict__ b_off,
                                const float* __restrict__ W_aw,
                                const float* __restrict__ b_aw)
{
    int i = blockIdx.x * blockDim.x + threadIdx.x;
    if (i < 128 * CDIM) {
        int n = i / CDIM, k = i % CDIM;
        float v = 0.f;
        if (n < 64)       v = W_off[k * 64 + n];
        else if (n < 96)  v = W_aw[k * 32 + (n - 64)];
        g_WcatT[i] = __float2half(v);
    }
    if (i < 128)
        g_bcat[i] = (i < 64) ? b_off[i] : (i < 96 ? b_aw[i - 64] : 0.f);
}

// ---------------------------------------------------------------------------
// Bilinear sampling (4 tokens/block, 64 threads/token), fp16 value -> fp16 attn
// ---------------------------------------------------------------------------
__global__ __launch_bounds__(256) void sample_kernel(
    const float* __restrict__ refp, __half* __restrict__ attn)
{
    __shared__ float s_oa[4][NOFFAW];
    __shared__ float2 s_ref[4];

    const int tid = threadIdx.x;
    const int lt  = tid >> 6;
    const int t64 = tid & 63;
    const int h   = t64 >> 3;
    const int l8  = t64 & 7;
    const long tok0 = (long)blockIdx.x * 4;

    if (tid < 96) {
        int ltt = tid / 24, e = (tid % 24) * 4;
        *(float4*)&s_oa[ltt][e] =
            *(const float4*)(g_offaw + (tok0 + ltt) * NOFFAW + e);
    } else if (tid < 100) {
        int j = tid - 96;
        s_ref[j] = ((const float2*)refp)[tok0 + j];
    }
    __syncthreads();

    const long token = tok0 + lt;
    const int  b     = (int)(token / LQ);
    const float* oa  = s_oa[lt];
    const float rx = s_ref[lt].x, ry = s_ref[lt].y;

    float l0 = oa[64 + h * 4 + 0], l1 = oa[64 + h * 4 + 1];
    float l2 = oa[64 + h * 4 + 2], l3 = oa[64 + h * 4 + 3];
    float mx = fmaxf(fmaxf(l0, l1), fmaxf(l2, l3));
    float e0 = __expf(l0 - mx), e1 = __expf(l1 - mx);
    float e2 = __expf(l2 - mx), e3 = __expf(l3 - mx);
    float inv = 1.f / (e0 + e1 + e2 + e3);
    float aww[4] = {e0 * inv, e1 * inv, e2 * inv, e3 * inv};

    const __half* vb = g_value_h + ((size_t)b * LQ) * CDIM + h * HD + l8 * 4;

    float4 acc = {0.f, 0.f, 0.f, 0.f};
#pragma unroll
    for (int p = 0; p < NPT; ++p) {
        float x = rx * WIMG + oa[(h * NPT + p) * 2 + 0] - 0.5f;
        float y = ry * HIMG + oa[(h * NPT + p) * 2 + 1] - 0.5f;
        float x0f = floorf(x), y0f = floorf(y);
        float fx = x - x0f, fy = y - y0f;
        int x0 = (int)x0f, y0 = (int)y0f;
        float a = aww[p];
        float w[4] = {a * (1.f - fx) * (1.f - fy), a * fx * (1.f - fy),
                      a * (1.f - fx) * fy,         a * fx * fy};
        int xs[4] = {x0, x0 + 1, x0,     x0 + 1};
        int ys[4] = {y0, y0,     y0 + 1, y0 + 1};
#pragma unroll
        for (int c = 0; c < 4; ++c) {
            int xi = xs[c], yi = ys[c];
            if (xi >= 0 && xi < WIMG && yi >= 0 && yi < HIMG && w[c] != 0.f) {
                const __half2* vp =
                    (const __half2*)(vb + (size_t)(yi * WIMG + xi) * CDIM);
                float2 u0 = __half22float2(vp[0]);
                float2 u1 = __half22float2(vp[1]);
                acc.x += u0.x * w[c]; acc.y += u0.y * w[c];
                acc.z += u1.x * w[c]; acc.w += u1.y * w[c];
            }
        }
    }
    __half* dst = attn + (size_t)token * CDIM + h * HD + l8 * 4;
    *(__half2*)(dst)     = __floats2half2_rn(acc.x, acc.y);
    *(__half2*)(dst + 2) = __floats2half2_rn(acc.z, acc.w);
}

// ---------------------------------------------------------------------------
// Launch
// ---------------------------------------------------------------------------
extern "C" void kernel_launch(void* const* d_in, const int* in_sizes, int n_in,
                              void* d_out, int out_size)
{
    const float* query = (const float*)d_in[0];
    const float* src   = (const float*)d_in[1];
    const float* refp  = (const float*)d_in[2];
    const float* W_off = (const float*)d_in[5];
    const float* b_off = (const float*)d_in[6];
    const float* W_aw  = (const float*)d_in[7];
    const float* b_aw  = (const float*)d_in[8];
    const float* W_val = (const float*)d_in[9];
    const float* b_val = (const float*)d_in[10];
    const float* W_out = (const float*)d_in[11];
    const float* b_out = (const float*)d_in[12];
    const float* g1    = (const float*)d_in[13];
    const float* be1   = (const float*)d_in[14];
    const float* W1    = (const float*)d_in[15];
    const float* b1    = (const float*)d_in[16];
    const float* W2    = (const float*)d_in[17];
    const float* b2    = (const float*)d_in[18];
    const float* g2    = (const float*)d_in[19];
    const float* be2   = (const float*)d_in[20];
    float* out = (float*)d_out;

    __half *p_src_h, *p_query_h, *p_value_h, *p_attn_h, *p_q2_h, *p_ffn_h;
    __half *p_WvalT, *p_WoutT, *p_W1T, *p_W2T;
    float *p_offaw, *p_q2, *p_bcat;
    cudaGetSymbolAddress((void**)&p_src_h,   g_src_h);
    cudaGetSymbolAddress((void**)&p_query_h, g_query_h);
    cudaGetSymbolAddress((void**)&p_value_h, g_value_h);
    cudaGetSymbolAddress((void**)&p_attn_h,  g_attn_h);
    cudaGetSymbolAddress((void**)&p_q2_h,    g_q2_h);
    cudaGetSymbolAddress((void**)&p_ffn_h,   g_ffn_h);
    cudaGetSymbolAddress((void**)&p_offaw,   g_offaw);
    cudaGetSymbolAddress((void**)&p_q2,      g_q2);
    cudaGetSymbolAddress((void**)&p_WvalT,   g_WvalT);
    cudaGetSymbolAddress((void**)&p_WoutT,   g_WoutT);
    cudaGetSymbolAddress((void**)&p_W1T,     g_W1T);
    cudaGetSymbolAddress((void**)&p_W2T,     g_W2T);
    __half* p_WcatT;
    cudaGetSymbolAddress((void**)&p_WcatT,   g_WcatT);
    cudaGetSymbolAddress((void**)&p_bcat,    g_bcat);

    cudaFuncSetAttribute(gemm_h_kernel<256, 0>,
                         cudaFuncAttributeMaxDynamicSharedMemorySize, SMEM_G256);
    cudaFuncSetAttribute(gemm_h_kernel<256, 1>,
                         cudaFuncAttributeMaxDynamicSharedMemorySize, SMEM_G256);
    cudaFuncSetAttribute(gemm_h_kernel<256, 2>,
                         cudaFuncAttributeMaxDynamicSharedMemorySize, SMEM_G256);
    cudaFuncSetAttribute(gemm_h_kernel<128, 0>,
                         cudaFuncAttributeMaxDynamicSharedMemorySize, SMEM_G128);

    const int MB = MTOK / BM;  // 625
    dim3 tb(32, 8);
    const long NELT = (long)MTOK * CDIM;

    // prep
    f2h_kernel<<<(int)((NELT / 4 + 255) / 256), 256>>>(src,   p_src_h,   NELT);
    f2h_kernel<<<(int)((NELT / 4 + 255) / 256), 256>>>(query, p_query_h, NELT);
    transpose_h_kernel<<<dim3(CDIM / 32, CDIM / 32), tb>>>(W_val, p_WvalT, CDIM, CDIM);
    transpose_h_kernel<<<dim3(CDIM / 32, CDIM / 32), tb>>>(W_out, p_WoutT, CDIM, CDIM);
    transpose_h_kernel<<<dim3(DFF / 32,  CDIM / 32), tb>>>(W1,    p_W1T,   CDIM, DFF);
    transpose_h_kernel<<<dim3(CDIM / 32, DFF / 32),  tb>>>(W2,    p_W2T,   DFF,  CDIM);
    concat_t_kernel<<<(128 * CDIM + 255) / 256, 256>>>(W_off, b_off, W_aw, b_aw);

    // main pipeline
    gemm_h_kernel<256, 1><<<dim3(1, MB), 256, SMEM_G256>>>(
        p_src_h, p_WvalT, b_val, p_value_h, CDIM, CDIM, 0,
        nullptr, nullptr, nullptr, nullptr);
    gemm_h_kernel<128, 0><<<dim3(1, MB), 256, SMEM_G128>>>(
        p_query_h, p_WcatT, p_bcat, p_offaw, NOFFAW, CDIM, 0,
        nullptr, nullptr, nullptr, nullptr);
    sample_kernel<<<MTOK / 4, 256>>>(refp, p_attn_h);
    // W_out proj + residual(query) + LN1 -> q2 (f32) and q2_h (fp16)
    gemm_h_kernel<256, 2><<<dim3(1, MB), 256, SMEM_G256>>>(
        p_attn_h, p_WoutT, b_out, p_q2, CDIM, CDIM, 0,
        query, g1, be1, p_q2_h);
    // FFN1 (relu, fp16 out)
    gemm_h_kernel<256, 1><<<dim3(DFF / 256, MB), 256, SMEM_G256>>>(
        p_q2_h, p_W1T, b1, p_ffn_h, DFF, CDIM, 1,
        nullptr, nullptr, nullptr, nullptr);
    // FFN2 + residual(q2) + LN2 -> final output
    gemm_h_kernel<256, 2><<<dim3(1, MB), 256, SMEM_G256>>>(
        p_ffn_h, p_W2T, b2, out, CDIM, DFF, 0,
        p_q2, g2, be2, nullptr);
}

// round 8
// speedup vs baseline: 6.2757x; 1.1419x over previous
#include <cuda_runtime.h>
#include <cuda_fp16.h>
#include <cstdint>

#define DEV_INLINE __device__ __forceinline__

constexpr int BB   = 8;
constexpr int LQ   = 10000;
constexpr int CDIM = 256;
constexpr int NHD  = 8;
constexpr int NPT  = 4;
constexpr int DFF  = 1024;
constexpr int HIMG = 100;
constexpr int WIMG = 100;
constexpr int HD   = 32;
constexpr int MTOK = BB * LQ;  // 80000
constexpr int NOFFAW = 96;

// fp16 activations
__device__ __half g_src_h  [MTOK * CDIM];
__device__ __half g_query_h[MTOK * CDIM];
__device__ __half g_value_h[MTOK * CDIM];
__device__ __half g_attn_h [MTOK * CDIM];
__device__ __half g_q2_h   [MTOK * CDIM];
__device__ __half g_ffn_h  [MTOK * DFF];
// fp32 buffers
__device__ float g_offaw[MTOK * NOFFAW];
__device__ float g_q2   [MTOK * CDIM];
// fp16 transposed weights [N][K]
__device__ __half g_WvalT[CDIM * CDIM];
__device__ __half g_WoutT[CDIM * CDIM];
__device__ __half g_W1T  [DFF * CDIM];
__device__ __half g_W2T  [CDIM * DFF];
__device__ __half g_WcatT[128 * CDIM];
__device__ float  g_bcat [128];

// ---------------------------------------------------------------------------
// MMA / ldmatrix helpers
// ---------------------------------------------------------------------------
DEV_INLINE void mma_f16(float* d, const uint32_t* a, const uint32_t* b) {
    asm volatile(
        "mma.sync.aligned.m16n8k16.row.col.f32.f16.f16.f32 "
        "{%0,%1,%2,%3}, {%4,%5,%6,%7}, {%8,%9}, {%0,%1,%2,%3};\n"
        : "+f"(d[0]), "+f"(d[1]), "+f"(d[2]), "+f"(d[3])
        : "r"(a[0]), "r"(a[1]), "r"(a[2]), "r"(a[3]), "r"(b[0]), "r"(b[1]));
}

DEV_INLINE void ldsm_x4(uint32_t* r, uint32_t addr) {
    asm volatile("ldmatrix.sync.aligned.m8n8.x4.shared.b16 {%0,%1,%2,%3}, [%4];"
                 : "=r"(r[0]), "=r"(r[1]), "=r"(r[2]), "=r"(r[3]) : "r"(addr));
}

DEV_INLINE void cp_async16(uint32_t dst, const void* src) {
    asm volatile("cp.async.cg.shared.global [%0], [%1], 16;\n" :: "r"(dst), "l"(src));
}

// ---------------------------------------------------------------------------
// fp16 tensor-core GEMM: acc = A[M,K] @ BT[N,K]^T
// MODE 0: f32 out  MODE 1: fp16 out  MODE 2: fused residual+LN (BN_=N=256)
// ---------------------------------------------------------------------------
constexpr int BM = 128, BK = 32;

template<int BN_, int MODE, int STG>
__global__ __launch_bounds__(256, (BN_ <= 128) ? 2 : 1) void gemm_h_kernel(
    const __half* __restrict__ A, const __half* __restrict__ BT,
    const float* __restrict__ bias, void* __restrict__ Cv,
    int N, int K, int relu,
    const float* __restrict__ resid, const float* __restrict__ gam,
    const float* __restrict__ bet, __half* __restrict__ out16)
{
    constexpr int WNT = BN_ / 4;
    constexpr int NI  = WNT / 8;
    constexpr int A_BYTES = BM * 64;
    constexpr int B_BYTES = BN_ * 64;
    constexpr int STAGE_BYTES = A_BYTES + B_BYTES;

    extern __shared__ char dsm[];
    uint32_t sm0 = (uint32_t)__cvta_generic_to_shared(dsm);

    __shared__ float s_bias[BN_];
    __shared__ float s_red[(MODE == 2) ? 128 : 1][8];
    __shared__ float s_g[(MODE == 2) ? 256 : 1], s_b[(MODE == 2) ? 256 : 1];

    const int tid  = threadIdx.x;
    const int lane = tid & 31;
    const int wid  = tid >> 5;
    const int wm   = wid >> 2;
    const int wn   = wid & 3;
    const size_t mbase = (size_t)blockIdx.y * BM;
    const int    nbase = blockIdx.x * BN_;

    const int g  = lane >> 3;
    const int rr = lane & 7;

    const int rowA = wm * 64 + rr + (g & 1) * 8;
    const uint32_t swA = (uint32_t)((rowA >> 1) & 3);
    const uint32_t aoff[2] = { (((0u + (g >> 1)) ^ swA) << 4),
                               (((2u + (g >> 1)) ^ swA) << 4) };
    const uint32_t aBase = (uint32_t)rowA * 64u;

    const int rowB = wn * WNT + rr + (g >> 1) * 8;
    const uint32_t swB = (uint32_t)((rowB >> 1) & 3);
    const uint32_t boff[2] = { (((0u + (g & 1)) ^ swB) << 4),
                               (((2u + (g & 1)) ^ swB) << 4) };
    const uint32_t bBase = (uint32_t)rowB * 64u;

    const int arow = tid >> 1;
    const int ac   = tid & 1;
    const __half* Ab = A + mbase * (size_t)K;

    for (int c = tid; c < BN_; c += 256) s_bias[c] = bias[nbase + c];

    float acc[4][NI][4];
#pragma unroll
    for (int mi = 0; mi < 4; ++mi)
#pragma unroll
        for (int ni = 0; ni < NI; ++ni)
#pragma unroll
            for (int j = 0; j < 4; ++j) acc[mi][ni][j] = 0.f;

    auto load_tile = [&](int stage, int k0) {
        uint32_t sA = sm0 + stage * STAGE_BYTES;
        uint32_t sB = sA + A_BYTES;
#pragma unroll
        for (int i = 0; i < 2; ++i) {
            int c = ac * 2 + i;
            cp_async16(sA + arow * 64 + ((c ^ ((arow >> 1) & 3)) << 4),
                       Ab + (size_t)arow * K + k0 + c * 8);
        }
#pragma unroll
        for (int it = 0; it < BN_ / 64; ++it) {
            int idx = tid + it * 256;
            int row = idx >> 2, c = idx & 3;
            cp_async16(sB + row * 64 + ((c ^ ((row >> 1) & 3)) << 4),
                       BT + (size_t)(nbase + row) * K + k0 + c * 8);
        }
    };

    const int ntiles = K / BK;

#pragma unroll
    for (int s = 0; s < STG - 1; ++s) {
        if (s < ntiles) load_tile(s, s * BK);
        asm volatile("cp.async.commit_group;\n");
    }
    asm volatile("cp.async.wait_group %0;\n" :: "n"(STG - 2));
    __syncthreads();

    int read_stage = 0, write_stage = STG - 1;

    for (int i = 0; i < ntiles; ++i) {
        uint32_t sA = sm0 + read_stage * STAGE_BYTES;
        uint32_t sB = sA + A_BYTES;

#pragma unroll
        for (int ks = 0; ks < 2; ++ks) {
            uint32_t afr[4][4], bfr[NI / 2][4];
#pragma unroll
            for (int mi = 0; mi < 4; ++mi)
                ldsm_x4(afr[mi], sA + aBase + mi * 1024 + aoff[ks]);
#pragma unroll
            for (int p = 0; p < NI / 2; ++p)
                ldsm_x4(bfr[p], sB + bBase + p * 1024 + boff[ks]);
#pragma unroll
            for (int mi = 0; mi < 4; ++mi)
#pragma unroll
                for (int ni = 0; ni < NI; ++ni)
                    mma_f16(acc[mi][ni], afr[mi], &bfr[ni >> 1][(ni & 1) * 2]);
        }

        if (i + STG - 1 < ntiles)
            load_tile(write_stage, (i + STG - 1) * BK);
        asm volatile("cp.async.commit_group;\n");
        asm volatile("cp.async.wait_group %0;\n" :: "n"(STG - 2));
        __syncthreads();

        if (++read_stage == STG)  read_stage = 0;
        if (++write_stage == STG) write_stage = 0;
    }

    if (MODE == 2) {
#pragma unroll
        for (int mi = 0; mi < 4; ++mi) {
            float psum0 = 0.f, psq0 = 0.f, psum1 = 0.f, psq1 = 0.f;
            size_t r0 = mbase + wm * 64 + mi * 16 + (lane >> 2);
            size_t r1 = r0 + 8;
#pragma unroll
            for (int ni = 0; ni < NI; ++ni) {
                int col = wn * WNT + ni * 8 + (lane & 3) * 2;
                float b0 = s_bias[col], b1 = s_bias[col + 1];
                float2 x0 = *(const float2*)(resid + r0 * 256 + col);
                float2 x1 = *(const float2*)(resid + r1 * 256 + col);
                float v0 = acc[mi][ni][0] + b0 + x0.x;
                float v1 = acc[mi][ni][1] + b1 + x0.y;
                float v2 = acc[mi][ni][2] + b0 + x1.x;
                float v3 = acc[mi][ni][3] + b1 + x1.y;
                acc[mi][ni][0] = v0; acc[mi][ni][1] = v1;
                acc[mi][ni][2] = v2; acc[mi][ni][3] = v3;
                psum0 += v0 + v1; psq0 += v0 * v0 + v1 * v1;
                psum1 += v2 + v3; psq1 += v2 * v2 + v3 * v3;
            }
#pragma unroll
            for (int o = 1; o <= 2; o <<= 1) {
                psum0 += __shfl_xor_sync(0xffffffffu, psum0, o);
                psq0  += __shfl_xor_sync(0xffffffffu, psq0,  o);
                psum1 += __shfl_xor_sync(0xffffffffu, psum1, o);
                psq1  += __shfl_xor_sync(0xffffffffu, psq1,  o);
            }
            if ((lane & 3) == 0) {
                int rl = wm * 64 + mi * 16 + (lane >> 2);
                s_red[rl][wn * 2] = psum0;     s_red[rl][wn * 2 + 1] = psq0;
                s_red[rl + 8][wn * 2] = psum1; s_red[rl + 8][wn * 2 + 1] = psq1;
            }
        }
        s_g[tid] = gam[tid];
        s_b[tid] = bet[tid];
        __syncthreads();

        float mstat[4][2][2];
#pragma unroll
        for (int mi = 0; mi < 4; ++mi) {
#pragma unroll
            for (int hh = 0; hh < 2; ++hh) {
                int rl = wm * 64 + mi * 16 + (lane >> 2) + hh * 8;
                float su = s_red[rl][0] + s_red[rl][2] + s_red[rl][4] + s_red[rl][6];
                float sq = s_red[rl][1] + s_red[rl][3] + s_red[rl][5] + s_red[rl][7];
                float m = su * (1.0f / 256);
                mstat[mi][hh][0] = m;
                mstat[mi][hh][1] = rsqrtf(sq * (1.0f / 256) - m * m + 1e-5f);
            }
        }

        float* C = (float*)Cv;
#pragma unroll
        for (int mi = 0; mi < 4; ++mi) {
            size_t r0 = mbase + wm * 64 + mi * 16 + (lane >> 2);
            size_t r1 = r0 + 8;
            float m0 = mstat[mi][0][0], s0 = mstat[mi][0][1];
            float m1 = mstat[mi][1][0], s1 = mstat[mi][1][1];
#pragma unroll
            for (int ni = 0; ni < NI; ++ni) {
                int col = wn * WNT + ni * 8 + (lane & 3) * 2;
                float g0 = s_g[col], g1v = s_g[col + 1];
                float be0 = s_b[col], be1 = s_b[col + 1];
                float o0 = (acc[mi][ni][0] - m0) * s0 * g0  + be0;
                float o1 = (acc[mi][ni][1] - m0) * s0 * g1v + be1;
                float o2 = (acc[mi][ni][2] - m1) * s1 * g0  + be0;
                float o3 = (acc[mi][ni][3] - m1) * s1 * g1v + be1;
                *(float2*)(C + r0 * 256 + col) = make_float2(o0, o1);
                *(float2*)(C + r1 * 256 + col) = make_float2(o2, o3);
                if (out16) {
                    *(__half2*)(out16 + r0 * 256 + col) = __floats2half2_rn(o0, o1);
                    *(__half2*)(out16 + r1 * 256 + col) = __floats2half2_rn(o2, o3);
                }
            }
        }
        return;
    }

#pragma unroll
    for (int mi = 0; mi < 4; ++mi) {
#pragma unroll
        for (int ni = 0; ni < NI; ++ni) {
            int col = nbase + wn * WNT + ni * 8 + (lane & 3) * 2;
            if (col >= N) continue;
            size_t r0 = mbase + wm * 64 + mi * 16 + (lane >> 2);
            size_t r1 = r0 + 8;
            float b0 = s_bias[col - nbase];
            float b1 = s_bias[col - nbase + 1];
            float v0 = acc[mi][ni][0] + b0;
            float v1 = acc[mi][ni][1] + b1;
            float v2 = acc[mi][ni][2] + b0;
            float v3 = acc[mi][ni][3] + b1;
            if (relu) {
                v0 = fmaxf(v0, 0.f); v1 = fmaxf(v1, 0.f);
                v2 = fmaxf(v2, 0.f); v3 = fmaxf(v3, 0.f);
            }
            if (MODE == 1) {
                __half* C = (__half*)Cv;
                *(__half2*)(C + r0 * (size_t)N + col) = __floats2half2_rn(v0, v1);
                *(__half2*)(C + r1 * (size_t)N + col) = __floats2half2_rn(v2, v3);
            } else {
                float* C = (float*)Cv;
                C[r0 * (size_t)N + col]     = v0;
                C[r0 * (size_t)N + col + 1] = v1;
                C[r1 * (size_t)N + col]     = v2;
                C[r1 * (size_t)N + col + 1] = v3;
            }
        }
    }
}

constexpr int SMEM_128_3 = 3 * (BM * 64 + 128 * 64);  // 49152
constexpr int SMEM_256_4 = 4 * (BM * 64 + 256 * 64);  // 98304

// ---------------------------------------------------------------------------
// fp32 -> fp16 conversion
// ---------------------------------------------------------------------------
__global__ void f2h_kernel(const float* __restrict__ in, __half* __restrict__ out,
                           long n)
{
    long i = ((long)blockIdx.x * blockDim.x + threadIdx.x) * 4;
    if (i < n) {
        float4 v = *(const float4*)(in + i);
        *(__half2*)(out + i)     = __floats2half2_rn(v.x, v.y);
        *(__half2*)(out + i + 2) = __floats2half2_rn(v.z, v.w);
    }
}

__global__ void transpose_h_kernel(const float* __restrict__ in,
                                   __half* __restrict__ out, int K, int N)
{
    __shared__ float t[32][33];
    int k0 = blockIdx.y * 32, n0 = blockIdx.x * 32;
    int x = threadIdx.x, y = threadIdx.y;
#pragma unroll
    for (int i = y; i < 32; i += 8)
        t[i][x] = in[(size_t)(k0 + i) * N + n0 + x];
    __syncthreads();
#pragma unroll
    for (int i = y; i < 32; i += 8)
        out[(size_t)(n0 + i) * K + k0 + x] = __float2half(t[x][i]);
}

__global__ void concat_t_kernel(const float* __restrict__ W_off,
                                const float* __restrict__ b_off,
                                const float* __restrict__ W_aw,
                                const float* __restrict__ b_aw)
{
    int i = blockIdx.x * blockDim.x + threadIdx.x;
    if (i < 128 * CDIM) {
        int n = i / CDIM, k = i % CDIM;
        float v = 0.f;
        if (n < 64)       v = W_off[k * 64 + n];
        else if (n < 96)  v = W_aw[k * 32 + (n - 64)];
        g_WcatT[i] = __float2half(v);
    }
    if (i < 128)
        g_bcat[i] = (i < 64) ? b_off[i] : (i < 96 ? b_aw[i - 64] : 0.f);
}

// ---------------------------------------------------------------------------
// Bilinear sampling
// ---------------------------------------------------------------------------
__global__ __launch_bounds__(256) void sample_kernel(
    const float* __restrict__ refp, __half* __restrict__ attn)
{
    __shared__ float s_oa[4][NOFFAW];
    __shared__ float2 s_ref[4];

    const int tid = threadIdx.x;
    const int lt  = tid >> 6;
    const int t64 = tid & 63;
    const int h   = t64 >> 3;
    const int l8  = t64 & 7;
    const long tok0 = (long)blockIdx.x * 4;

    if (tid < 96) {
        int ltt = tid / 24, e = (tid % 24) * 4;
        *(float4*)&s_oa[ltt][e] =
            *(const float4*)(g_offaw + (tok0 + ltt) * NOFFAW + e);
    } else if (tid < 100) {
        int j = tid - 96;
        s_ref[j] = ((const float2*)refp)[tok0 + j];
    }
    __syncthreads();

    const long token = tok0 + lt;
    const int  b     = (int)(token / LQ);
    const float* oa  = s_oa[lt];
    const float rx = s_ref[lt].x, ry = s_ref[lt].y;

    float l0 = oa[64 + h * 4 + 0], l1 = oa[64 + h * 4 + 1];
    float l2 = oa[64 + h * 4 + 2], l3 = oa[64 + h * 4 + 3];
    float mx = fmaxf(fmaxf(l0, l1), fmaxf(l2, l3));
    float e0 = __expf(l0 - mx), e1 = __expf(l1 - mx);
    float e2 = __expf(l2 - mx), e3 = __expf(l3 - mx);
    float inv = 1.f / (e0 + e1 + e2 + e3);
    float aww[4] = {e0 * inv, e1 * inv, e2 * inv, e3 * inv};

    const __half* vb = g_value_h + ((size_t)b * LQ) * CDIM + h * HD + l8 * 4;

    float4 acc = {0.f, 0.f, 0.f, 0.f};
#pragma unroll
    for (int p = 0; p < NPT; ++p) {
        float x = rx * WIMG + oa[(h * NPT + p) * 2 + 0] - 0.5f;
        float y = ry * HIMG + oa[(h * NPT + p) * 2 + 1] - 0.5f;
        float x0f = floorf(x), y0f = floorf(y);
        float fx = x - x0f, fy = y - y0f;
        int x0 = (int)x0f, y0 = (int)y0f;
        float a = aww[p];
        float w[4] = {a * (1.f - fx) * (1.f - fy), a * fx * (1.f - fy),
                      a * (1.f - fx) * fy,         a * fx * fy};
        int xs[4] = {x0, x0 + 1, x0,     x0 + 1};
        int ys[4] = {y0, y0,     y0 + 1, y0 + 1};
#pragma unroll
        for (int c = 0; c < 4; ++c) {
            int xi = xs[c], yi = ys[c];
            if (xi >= 0 && xi < WIMG && yi >= 0 && yi < HIMG && w[c] != 0.f) {
                const __half2* vp =
                    (const __half2*)(vb + (size_t)(yi * WIMG + xi) * CDIM);
                float2 u0 = __half22float2(vp[0]);
                float2 u1 = __half22float2(vp[1]);
                acc.x += u0.x * w[c]; acc.y += u0.y * w[c];
                acc.z += u1.x * w[c]; acc.w += u1.y * w[c];
            }
        }
    }
    __half* dst = attn + (size_t)token * CDIM + h * HD + l8 * 4;
    *(__half2*)(dst)     = __floats2half2_rn(acc.x, acc.y);
    *(__half2*)(dst + 2) = __floats2half2_rn(acc.z, acc.w);
}

// ---------------------------------------------------------------------------
// Launch (two-stream overlap of the front section)
// ---------------------------------------------------------------------------
extern "C" void kernel_launch(void* const* d_in, const int* in_sizes, int n_in,
                              void* d_out, int out_size)
{
    const float* query = (const float*)d_in[0];
    const float* src   = (const float*)d_in[1];
    const float* refp  = (const float*)d_in[2];
    const float* W_off = (const float*)d_in[5];
    const float* b_off = (const float*)d_in[6];
    const float* W_aw  = (const float*)d_in[7];
    const float* b_aw  = (const float*)d_in[8];
    const float* W_val = (const float*)d_in[9];
    const float* b_val = (const float*)d_in[10];
    const float* W_out = (const float*)d_in[11];
    const float* b_out = (const float*)d_in[12];
    const float* g1    = (const float*)d_in[13];
    const float* be1   = (const float*)d_in[14];
    const float* W1    = (const float*)d_in[15];
    const float* b1    = (const float*)d_in[16];
    const float* W2    = (const float*)d_in[17];
    const float* b2    = (const float*)d_in[18];
    const float* g2    = (const float*)d_in[19];
    const float* be2   = (const float*)d_in[20];
    float* out = (float*)d_out;

    __half *p_src_h, *p_query_h, *p_value_h, *p_attn_h, *p_q2_h, *p_ffn_h;
    __half *p_WvalT, *p_WoutT, *p_W1T, *p_W2T, *p_WcatT;
    float *p_offaw, *p_q2, *p_bcat;
    cudaGetSymbolAddress((void**)&p_src_h,   g_src_h);
    cudaGetSymbolAddress((void**)&p_query_h, g_query_h);
    cudaGetSymbolAddress((void**)&p_value_h, g_value_h);
    cudaGetSymbolAddress((void**)&p_attn_h,  g_attn_h);
    cudaGetSymbolAddress((void**)&p_q2_h,    g_q2_h);
    cudaGetSymbolAddress((void**)&p_ffn_h,   g_ffn_h);
    cudaGetSymbolAddress((void**)&p_offaw,   g_offaw);
    cudaGetSymbolAddress((void**)&p_q2,      g_q2);
    cudaGetSymbolAddress((void**)&p_WvalT,   g_WvalT);
    cudaGetSymbolAddress((void**)&p_WoutT,   g_WoutT);
    cudaGetSymbolAddress((void**)&p_W1T,     g_W1T);
    cudaGetSymbolAddress((void**)&p_W2T,     g_W2T);
    cudaGetSymbolAddress((void**)&p_WcatT,   g_WcatT);
    cudaGetSymbolAddress((void**)&p_bcat,    g_bcat);

    static cudaStream_t s1 = nullptr;
    static cudaEvent_t evFork = nullptr, evB = nullptr, evC = nullptr;
    static bool attr_done = false;
    if (!s1) {
        cudaStreamCreateWithFlags(&s1, cudaStreamNonBlocking);
        cudaEventCreateWithFlags(&evFork, cudaEventDisableTiming);
        cudaEventCreateWithFlags(&evB,    cudaEventDisableTiming);
        cudaEventCreateWithFlags(&evC,    cudaEventDisableTiming);
    }
    if (!attr_done) {
        cudaFuncSetAttribute(gemm_h_kernel<128, 0, 3>,
                             cudaFuncAttributeMaxDynamicSharedMemorySize, SMEM_128_3);
        cudaFuncSetAttribute(gemm_h_kernel<128, 1, 3>,
                             cudaFuncAttributeMaxDynamicSharedMemorySize, SMEM_128_3);
        cudaFuncSetAttribute(gemm_h_kernel<256, 2, 4>,
                             cudaFuncAttributeMaxDynamicSharedMemorySize, SMEM_256_4);
        attr_done = true;
    }

    const int MB = MTOK / BM;  // 625
    dim3 tb(32, 8);
    const long NELT = (long)MTOK * CDIM;
    const int F2H_GRID = (int)((NELT / 4 + 255) / 256);

    // ---- fork ----
    cudaEventRecord(evFork, 0);
    cudaStreamWaitEvent(s1, evFork, 0);

    // stream B: query-side chain + later-needed weight preps
    f2h_kernel<<<F2H_GRID, 256, 0, s1>>>(query, p_query_h, NELT);
    concat_t_kernel<<<(128 * CDIM + 255) / 256, 256, 0, s1>>>(W_off, b_off, W_aw, b_aw);
    gemm_h_kernel<128, 0, 3><<<dim3(1, MB), 256, SMEM_128_3, s1>>>(
        p_query_h, p_WcatT, p_bcat, p_offaw, NOFFAW, CDIM, 0,
        nullptr, nullptr, nullptr, nullptr);
    cudaEventRecord(evB, s1);
    transpose_h_kernel<<<dim3(CDIM / 32, CDIM / 32), tb, 0, s1>>>(W_out, p_WoutT, CDIM, CDIM);
    transpose_h_kernel<<<dim3(DFF / 32,  CDIM / 32), tb, 0, s1>>>(W1, p_W1T, CDIM, DFF);
    transpose_h_kernel<<<dim3(CDIM / 32, DFF / 32),  tb, 0, s1>>>(W2, p_W2T, DFF, CDIM);
    cudaEventRecord(evC, s1);

    // stream A (default): src-side chain
    f2h_kernel<<<F2H_GRID, 256>>>(src, p_src_h, NELT);
    transpose_h_kernel<<<dim3(CDIM / 32, CDIM / 32), tb>>>(W_val, p_WvalT, CDIM, CDIM);
    gemm_h_kernel<128, 1, 3><<<dim3(2, MB), 256, SMEM_128_3>>>(
        p_src_h, p_WvalT, b_val, p_value_h, CDIM, CDIM, 0,
        nullptr, nullptr, nullptr, nullptr);

    // ---- join: sample needs value (A) + offaw (B) ----
    cudaStreamWaitEvent(0, evB, 0);
    sample_kernel<<<MTOK / 4, 256>>>(refp, p_attn_h);

    cudaStreamWaitEvent(0, evC, 0);
    // W_out proj + residual(query) + LN1 -> q2 / q2_h
    gemm_h_kernel<256, 2, 4><<<dim3(1, MB), 256, SMEM_256_4>>>(
        p_attn_h, p_WoutT, b_out, p_q2, CDIM, CDIM, 0,
        query, g1, be1, p_q2_h);
    // FFN1 (relu, fp16 out)
    gemm_h_kernel<128, 1, 3><<<dim3(DFF / 128, MB), 256, SMEM_128_3>>>(
        p_q2_h, p_W1T, b1, p_ffn_h, DFF, CDIM, 1,
        nullptr, nullptr, nullptr, nullptr);
    // FFN2 + residual(q2) + LN2 -> final output
    gemm_h_kernel<256, 2, 4><<<dim3(1, MB), 256, SMEM_256_4>>>(
        p_ffn_h, p_W2T, b2, out, CDIM, DFF, 0,
        p_q2, g2, be2, nullptr);
}

// round 9
// speedup vs baseline: 6.4616x; 1.0296x over previous
#include <cuda_runtime.h>
#include <cuda_fp16.h>
#include <cstdint>

#define DEV_INLINE __device__ __forceinline__

constexpr int BB   = 8;
constexpr int LQ   = 10000;
constexpr int CDIM = 256;
constexpr int NHD  = 8;
constexpr int NPT  = 4;
constexpr int DFF  = 1024;
constexpr int HIMG = 100;
constexpr int WIMG = 100;
constexpr int HD   = 32;
constexpr int MTOK = BB * LQ;  // 80000
constexpr int NOFFAW = 96;

// fp16 activations
__device__ __half g_src_h  [MTOK * CDIM];
__device__ __half g_query_h[MTOK * CDIM];
__device__ __half g_value_h[MTOK * CDIM];
__device__ __half g_attn_h [MTOK * CDIM];
__device__ __half g_q2_h   [MTOK * CDIM];
__device__ __half g_ffn_h  [MTOK * DFF];
// fp32 buffers
__device__ float g_offaw[MTOK * NOFFAW];
__device__ float g_q2   [MTOK * CDIM];
// fp16 transposed weights [N][K]
__device__ __half g_WvalT[CDIM * CDIM];
__device__ __half g_WoutT[CDIM * CDIM];
__device__ __half g_W1T  [DFF * CDIM];
__device__ __half g_W2T  [CDIM * DFF];
__device__ __half g_WcatT[128 * CDIM];
__device__ float  g_bcat [128];

// ---------------------------------------------------------------------------
// MMA / ldmatrix helpers
// ---------------------------------------------------------------------------
DEV_INLINE void mma_f16(float* d, const uint32_t* a, const uint32_t* b) {
    asm volatile(
        "mma.sync.aligned.m16n8k16.row.col.f32.f16.f16.f32 "
        "{%0,%1,%2,%3}, {%4,%5,%6,%7}, {%8,%9}, {%0,%1,%2,%3};\n"
        : "+f"(d[0]), "+f"(d[1]), "+f"(d[2]), "+f"(d[3])
        : "r"(a[0]), "r"(a[1]), "r"(a[2]), "r"(a[3]), "r"(b[0]), "r"(b[1]));
}

DEV_INLINE void ldsm_x4(uint32_t* r, uint32_t addr) {
    asm volatile("ldmatrix.sync.aligned.m8n8.x4.shared.b16 {%0,%1,%2,%3}, [%4];"
                 : "=r"(r[0]), "=r"(r[1]), "=r"(r[2]), "=r"(r[3]) : "r"(addr));
}

DEV_INLINE void cp_async16(uint32_t dst, const void* src) {
    asm volatile("cp.async.cg.shared.global [%0], [%1], 16;\n" :: "r"(dst), "l"(src));
}

// ---------------------------------------------------------------------------
// fp16 tensor-core GEMM: acc = A[M,K] @ BT[N,K]^T  (rows offset by mrow0)
// MODE 0: f32 out  MODE 1: fp16 out  MODE 2: fused residual+LN (BN_=N=256)
// ---------------------------------------------------------------------------
constexpr int BM = 128, BK = 32;

template<int BN_, int MODE, int STG>
__global__ __launch_bounds__(256, (BN_ <= 128) ? 2 : 1) void gemm_h_kernel(
    const __half* __restrict__ A, const __half* __restrict__ BT,
    const float* __restrict__ bias, void* __restrict__ Cv,
    int N, int K, int relu,
    const float* __restrict__ resid, const float* __restrict__ gam,
    const float* __restrict__ bet, __half* __restrict__ out16,
    int mrow0)
{
    constexpr int WNT = BN_ / 4;
    constexpr int NI  = WNT / 8;
    constexpr int A_BYTES = BM * 64;
    constexpr int B_BYTES = BN_ * 64;
    constexpr int STAGE_BYTES = A_BYTES + B_BYTES;

    extern __shared__ char dsm[];
    uint32_t sm0 = (uint32_t)__cvta_generic_to_shared(dsm);

    __shared__ float s_bias[BN_];
    __shared__ float s_red[(MODE == 2) ? 128 : 1][8];
    __shared__ float s_g[(MODE == 2) ? 256 : 1], s_b[(MODE == 2) ? 256 : 1];

    const int tid  = threadIdx.x;
    const int lane = tid & 31;
    const int wid  = tid >> 5;
    const int wm   = wid >> 2;
    const int wn   = wid & 3;
    const size_t mbase = (size_t)mrow0 + (size_t)blockIdx.y * BM;
    const int    nbase = blockIdx.x * BN_;

    const int g  = lane >> 3;
    const int rr = lane & 7;

    const int rowA = wm * 64 + rr + (g & 1) * 8;
    const uint32_t swA = (uint32_t)((rowA >> 1) & 3);
    const uint32_t aoff[2] = { (((0u + (g >> 1)) ^ swA) << 4),
                               (((2u + (g >> 1)) ^ swA) << 4) };
    const uint32_t aBase = (uint32_t)rowA * 64u;

    const int rowB = wn * WNT + rr + (g >> 1) * 8;
    const uint32_t swB = (uint32_t)((rowB >> 1) & 3);
    const uint32_t boff[2] = { (((0u + (g & 1)) ^ swB) << 4),
                               (((2u + (g & 1)) ^ swB) << 4) };
    const uint32_t bBase = (uint32_t)rowB * 64u;

    const int arow = tid >> 1;
    const int ac   = tid & 1;
    const __half* Ab = A + mbase * (size_t)K;

    for (int c = tid; c < BN_; c += 256) s_bias[c] = bias[nbase + c];

    float acc[4][NI][4];
#pragma unroll
    for (int mi = 0; mi < 4; ++mi)
#pragma unroll
        for (int ni = 0; ni < NI; ++ni)
#pragma unroll
            for (int j = 0; j < 4; ++j) acc[mi][ni][j] = 0.f;

    auto load_tile = [&](int stage, int k0) {
        uint32_t sA = sm0 + stage * STAGE_BYTES;
        uint32_t sB = sA + A_BYTES;
#pragma unroll
        for (int i = 0; i < 2; ++i) {
            int c = ac * 2 + i;
            cp_async16(sA + arow * 64 + ((c ^ ((arow >> 1) & 3)) << 4),
                       Ab + (size_t)arow * K + k0 + c * 8);
        }
#pragma unroll
        for (int it = 0; it < BN_ / 64; ++it) {
            int idx = tid + it * 256;
            int row = idx >> 2, c = idx & 3;
            cp_async16(sB + row * 64 + ((c ^ ((row >> 1) & 3)) << 4),
                       BT + (size_t)(nbase + row) * K + k0 + c * 8);
        }
    };

    const int ntiles = K / BK;

#pragma unroll
    for (int s = 0; s < STG - 1; ++s) {
        if (s < ntiles) load_tile(s, s * BK);
        asm volatile("cp.async.commit_group;\n");
    }
    asm volatile("cp.async.wait_group %0;\n" :: "n"(STG - 2));
    __syncthreads();

    int read_stage = 0, write_stage = STG - 1;

    for (int i = 0; i < ntiles; ++i) {
        uint32_t sA = sm0 + read_stage * STAGE_BYTES;
        uint32_t sB = sA + A_BYTES;

#pragma unroll
        for (int ks = 0; ks < 2; ++ks) {
            uint32_t afr[4][4], bfr[NI / 2][4];
#pragma unroll
            for (int mi = 0; mi < 4; ++mi)
                ldsm_x4(afr[mi], sA + aBase + mi * 1024 + aoff[ks]);
#pragma unroll
            for (int p = 0; p < NI / 2; ++p)
                ldsm_x4(bfr[p], sB + bBase + p * 1024 + boff[ks]);
#pragma unroll
            for (int mi = 0; mi < 4; ++mi)
#pragma unroll
                for (int ni = 0; ni < NI; ++ni)
                    mma_f16(acc[mi][ni], afr[mi], &bfr[ni >> 1][(ni & 1) * 2]);
        }

        if (i + STG - 1 < ntiles)
            load_tile(write_stage, (i + STG - 1) * BK);
        asm volatile("cp.async.commit_group;\n");
        asm volatile("cp.async.wait_group %0;\n" :: "n"(STG - 2));
        __syncthreads();

        if (++read_stage == STG)  read_stage = 0;
        if (++write_stage == STG) write_stage = 0;
    }

    if (MODE == 2) {
#pragma unroll
        for (int mi = 0; mi < 4; ++mi) {
            float psum0 = 0.f, psq0 = 0.f, psum1 = 0.f, psq1 = 0.f;
            size_t r0 = mbase + wm * 64 + mi * 16 + (lane >> 2);
            size_t r1 = r0 + 8;
#pragma unroll
            for (int ni = 0; ni < NI; ++ni) {
                int col = wn * WNT + ni * 8 + (lane & 3) * 2;
                float b0 = s_bias[col], b1 = s_bias[col + 1];
                float2 x0 = *(const float2*)(resid + r0 * 256 + col);
                float2 x1 = *(const float2*)(resid + r1 * 256 + col);
                float v0 = acc[mi][ni][0] + b0 + x0.x;
                float v1 = acc[mi][ni][1] + b1 + x0.y;
                float v2 = acc[mi][ni][2] + b0 + x1.x;
                float v3 = acc[mi][ni][3] + b1 + x1.y;
                acc[mi][ni][0] = v0; acc[mi][ni][1] = v1;
                acc[mi][ni][2] = v2; acc[mi][ni][3] = v3;
                psum0 += v0 + v1; psq0 += v0 * v0 + v1 * v1;
                psum1 += v2 + v3; psq1 += v2 * v2 + v3 * v3;
            }
#pragma unroll
            for (int o = 1; o <= 2; o <<= 1) {
                psum0 += __shfl_xor_sync(0xffffffffu, psum0, o);
                psq0  += __shfl_xor_sync(0xffffffffu, psq0,  o);
                psum1 += __shfl_xor_sync(0xffffffffu, psum1, o);
                psq1  += __shfl_xor_sync(0xffffffffu, psq1,  o);
            }
            if ((lane & 3) == 0) {
                int rl = wm * 64 + mi * 16 + (lane >> 2);
                s_red[rl][wn * 2] = psum0;     s_red[rl][wn * 2 + 1] = psq0;
                s_red[rl + 8][wn * 2] = psum1; s_red[rl + 8][wn * 2 + 1] = psq1;
            }
        }
        s_g[tid] = gam[tid];
        s_b[tid] = bet[tid];
        __syncthreads();

        float mstat[4][2][2];
#pragma unroll
        for (int mi = 0; mi < 4; ++mi) {
#pragma unroll
            for (int hh = 0; hh < 2; ++hh) {
                int rl = wm * 64 + mi * 16 + (lane >> 2) + hh * 8;
                float su = s_red[rl][0] + s_red[rl][2] + s_red[rl][4] + s_red[rl][6];
                float sq = s_red[rl][1] + s_red[rl][3] + s_red[rl][5] + s_red[rl][7];
                float m = su * (1.0f / 256);
                mstat[mi][hh][0] = m;
                mstat[mi][hh][1] = rsqrtf(sq * (1.0f / 256) - m * m + 1e-5f);
            }
        }

        float* C = (float*)Cv;
#pragma unroll
        for (int mi = 0; mi < 4; ++mi) {
            size_t r0 = mbase + wm * 64 + mi * 16 + (lane >> 2);
            size_t r1 = r0 + 8;
            float m0 = mstat[mi][0][0], s0 = mstat[mi][0][1];
            float m1 = mstat[mi][1][0], s1 = mstat[mi][1][1];
#pragma unroll
            for (int ni = 0; ni < NI; ++ni) {
                int col = wn * WNT + ni * 8 + (lane & 3) * 2;
                float g0 = s_g[col], g1v = s_g[col + 1];
                float be0 = s_b[col], be1 = s_b[col + 1];
                float o0 = (acc[mi][ni][0] - m0) * s0 * g0  + be0;
                float o1 = (acc[mi][ni][1] - m0) * s0 * g1v + be1;
                float o2 = (acc[mi][ni][2] - m1) * s1 * g0  + be0;
                float o3 = (acc[mi][ni][3] - m1) * s1 * g1v + be1;
                *(float2*)(C + r0 * 256 + col) = make_float2(o0, o1);
                *(float2*)(C + r1 * 256 + col) = make_float2(o2, o3);
                if (out16) {
                    *(__half2*)(out16 + r0 * 256 + col) = __floats2half2_rn(o0, o1);
                    *(__half2*)(out16 + r1 * 256 + col) = __floats2half2_rn(o2, o3);
                }
            }
        }
        return;
    }

#pragma unroll
    for (int mi = 0; mi < 4; ++mi) {
#pragma unroll
        for (int ni = 0; ni < NI; ++ni) {
            int col = nbase + wn * WNT + ni * 8 + (lane & 3) * 2;
            if (col >= N) continue;
            size_t r0 = mbase + wm * 64 + mi * 16 + (lane >> 2);
            size_t r1 = r0 + 8;
            float b0 = s_bias[col - nbase];
            float b1 = s_bias[col - nbase + 1];
            float v0 = acc[mi][ni][0] + b0;
            float v1 = acc[mi][ni][1] + b1;
            float v2 = acc[mi][ni][2] + b0;
            float v3 = acc[mi][ni][3] + b1;
            if (relu) {
                v0 = fmaxf(v0, 0.f); v1 = fmaxf(v1, 0.f);
                v2 = fmaxf(v2, 0.f); v3 = fmaxf(v3, 0.f);
            }
            if (MODE == 1) {
                __half* C = (__half*)Cv;
                *(__half2*)(C + r0 * (size_t)N + col) = __floats2half2_rn(v0, v1);
                *(__half2*)(C + r1 * (size_t)N + col) = __floats2half2_rn(v2, v3);
            } else {
                float* C = (float*)Cv;
                C[r0 * (size_t)N + col]     = v0;
                C[r0 * (size_t)N + col + 1] = v1;
                C[r1 * (size_t)N + col]     = v2;
                C[r1 * (size_t)N + col + 1] = v3;
            }
        }
    }
}

constexpr int SMEM_128_3 = 3 * (BM * 64 + 128 * 64);  // 49152
constexpr int SMEM_256_4 = 4 * (BM * 64 + 256 * 64);  // 98304

// ---------------------------------------------------------------------------
// fp32 -> fp16 conversion
// ---------------------------------------------------------------------------
__global__ void f2h_kernel(const float* __restrict__ in, __half* __restrict__ out,
                           long n)
{
    long i = ((long)blockIdx.x * blockDim.x + threadIdx.x) * 4;
    if (i < n) {
        float4 v = *(const float4*)(in + i);
        *(__half2*)(out + i)     = __floats2half2_rn(v.x, v.y);
        *(__half2*)(out + i + 2) = __floats2half2_rn(v.z, v.w);
    }
}

__global__ void transpose_h_kernel(const float* __restrict__ in,
                                   __half* __restrict__ out, int K, int N)
{
    __shared__ float t[32][33];
    int k0 = blockIdx.y * 32, n0 = blockIdx.x * 32;
    int x = threadIdx.x, y = threadIdx.y;
#pragma unroll
    for (int i = y; i < 32; i += 8)
        t[i][x] = in[(size_t)(k0 + i) * N + n0 + x];
    __syncthreads();
#pragma unroll
    for (int i = y; i < 32; i += 8)
        out[(size_t)(n0 + i) * K + k0 + x] = __float2half(t[x][i]);
}

__global__ void concat_t_kernel(const float* __restrict__ W_off,
                                const float* __restrict__ b_off,
                                const float* __restrict__ W_aw,
                                const float* __restrict__ b_aw)
{
    int i = blockIdx.x * blockDim.x + threadIdx.x;
    if (i < 128 * CDIM) {
        int n = i / CDIM, k = i % CDIM;
        float v = 0.f;
        if (n < 64)       v = W_off[k * 64 + n];
        else if (n < 96)  v = W_aw[k * 32 + (n - 64)];
        g_WcatT[i] = __float2half(v);
    }
    if (i < 128)
        g_bcat[i] = (i < 64) ? b_off[i] : (i < 96 ? b_aw[i - 64] : 0.f);
}

// ---------------------------------------------------------------------------
// Bilinear sampling (token range offset by tokbase)
// ---------------------------------------------------------------------------
__global__ __launch_bounds__(256) void sample_kernel(
    const float* __restrict__ refp, __half* __restrict__ attn, long tokbase)
{
    __shared__ float s_oa[4][NOFFAW];
    __shared__ float2 s_ref[4];

    const int tid = threadIdx.x;
    const int lt  = tid >> 6;
    const int t64 = tid & 63;
    const int h   = t64 >> 3;
    const int l8  = t64 & 7;
    const long tok0 = tokbase + (long)blockIdx.x * 4;

    if (tid < 96) {
        int ltt = tid / 24, e = (tid % 24) * 4;
        *(float4*)&s_oa[ltt][e] =
            *(const float4*)(g_offaw + (tok0 + ltt) * NOFFAW + e);
    } else if (tid < 100) {
        int j = tid - 96;
        s_ref[j] = ((const float2*)refp)[tok0 + j];
    }
    __syncthreads();

    const long token = tok0 + lt;
    const int  b     = (int)(token / LQ);
    const float* oa  = s_oa[lt];
    const float rx = s_ref[lt].x, ry = s_ref[lt].y;

    float l0 = oa[64 + h * 4 + 0], l1 = oa[64 + h * 4 + 1];
    float l2 = oa[64 + h * 4 + 2], l3 = oa[64 + h * 4 + 3];
    float mx = fmaxf(fmaxf(l0, l1), fmaxf(l2, l3));
    float e0 = __expf(l0 - mx), e1 = __expf(l1 - mx);
    float e2 = __expf(l2 - mx), e3 = __expf(l3 - mx);
    float inv = 1.f / (e0 + e1 + e2 + e3);
    float aww[4] = {e0 * inv, e1 * inv, e2 * inv, e3 * inv};

    const __half* vb = g_value_h + ((size_t)b * LQ) * CDIM + h * HD + l8 * 4;

    float4 acc = {0.f, 0.f, 0.f, 0.f};
#pragma unroll
    for (int p = 0; p < NPT; ++p) {
        float x = rx * WIMG + oa[(h * NPT + p) * 2 + 0] - 0.5f;
        float y = ry * HIMG + oa[(h * NPT + p) * 2 + 1] - 0.5f;
        float x0f = floorf(x), y0f = floorf(y);
        float fx = x - x0f, fy = y - y0f;
        int x0 = (int)x0f, y0 = (int)y0f;
        float a = aww[p];
        float w[4] = {a * (1.f - fx) * (1.f - fy), a * fx * (1.f - fy),
                      a * (1.f - fx) * fy,         a * fx * fy};
        int xs[4] = {x0, x0 + 1, x0,     x0 + 1};
        int ys[4] = {y0, y0,     y0 + 1, y0 + 1};
#pragma unroll
        for (int c = 0; c < 4; ++c) {
            int xi = xs[c], yi = ys[c];
            if (xi >= 0 && xi < WIMG && yi >= 0 && yi < HIMG && w[c] != 0.f) {
                const __half2* vp =
                    (const __half2*)(vb + (size_t)(yi * WIMG + xi) * CDIM);
                float2 u0 = __half22float2(vp[0]);
                float2 u1 = __half22float2(vp[1]);
                acc.x += u0.x * w[c]; acc.y += u0.y * w[c];
                acc.z += u1.x * w[c]; acc.w += u1.y * w[c];
            }
        }
    }
    __half* dst = attn + (size_t)token * CDIM + h * HD + l8 * 4;
    *(__half2*)(dst)     = __floats2half2_rn(acc.x, acc.y);
    *(__half2*)(dst + 2) = __floats2half2_rn(acc.z, acc.w);
}

// ---------------------------------------------------------------------------
// Launch: two-stream prep overlap + two-chunk pipelined back half
// ---------------------------------------------------------------------------
extern "C" void kernel_launch(void* const* d_in, const int* in_sizes, int n_in,
                              void* d_out, int out_size)
{
    const float* query = (const float*)d_in[0];
    const float* src   = (const float*)d_in[1];
    const float* refp  = (const float*)d_in[2];
    const float* W_off = (const float*)d_in[5];
    const float* b_off = (const float*)d_in[6];
    const float* W_aw  = (const float*)d_in[7];
    const float* b_aw  = (const float*)d_in[8];
    const float* W_val = (const float*)d_in[9];
    const float* b_val = (const float*)d_in[10];
    const float* W_out = (const float*)d_in[11];
    const float* b_out = (const float*)d_in[12];
    const float* g1    = (const float*)d_in[13];
    const float* be1   = (const float*)d_in[14];
    const float* W1    = (const float*)d_in[15];
    const float* b1    = (const float*)d_in[16];
    const float* W2    = (const float*)d_in[17];
    const float* b2    = (const float*)d_in[18];
    const float* g2    = (const float*)d_in[19];
    const float* be2   = (const float*)d_in[20];
    float* out = (float*)d_out;

    __half *p_src_h, *p_query_h, *p_value_h, *p_attn_h, *p_q2_h, *p_ffn_h;
    __half *p_WvalT, *p_WoutT, *p_W1T, *p_W2T, *p_WcatT;
    float *p_offaw, *p_q2, *p_bcat;
    cudaGetSymbolAddress((void**)&p_src_h,   g_src_h);
    cudaGetSymbolAddress((void**)&p_query_h, g_query_h);
    cudaGetSymbolAddress((void**)&p_value_h, g_value_h);
    cudaGetSymbolAddress((void**)&p_attn_h,  g_attn_h);
    cudaGetSymbolAddress((void**)&p_q2_h,    g_q2_h);
    cudaGetSymbolAddress((void**)&p_ffn_h,   g_ffn_h);
    cudaGetSymbolAddress((void**)&p_offaw,   g_offaw);
    cudaGetSymbolAddress((void**)&p_q2,      g_q2);
    cudaGetSymbolAddress((void**)&p_WvalT,   g_WvalT);
    cudaGetSymbolAddress((void**)&p_WoutT,   g_WoutT);
    cudaGetSymbolAddress((void**)&p_W1T,     g_W1T);
    cudaGetSymbolAddress((void**)&p_W2T,     g_W2T);
    cudaGetSymbolAddress((void**)&p_WcatT,   g_WcatT);
    cudaGetSymbolAddress((void**)&p_bcat,    g_bcat);

    static cudaStream_t s1 = nullptr;
    static cudaEvent_t evFork = nullptr, evB = nullptr, evC = nullptr,
                       evVal = nullptr, evD = nullptr;
    static bool attr_done = false;
    if (!s1) {
        cudaStreamCreateWithFlags(&s1, cudaStreamNonBlocking);
        cudaEventCreateWithFlags(&evFork, cudaEventDisableTiming);
        cudaEventCreateWithFlags(&evB,    cudaEventDisableTiming);
        cudaEventCreateWithFlags(&evC,    cudaEventDisableTiming);
        cudaEventCreateWithFlags(&evVal,  cudaEventDisableTiming);
        cudaEventCreateWithFlags(&evD,    cudaEventDisableTiming);
    }
    if (!attr_done) {
        cudaFuncSetAttribute(gemm_h_kernel<128, 0, 3>,
                             cudaFuncAttributeMaxDynamicSharedMemorySize, SMEM_128_3);
        cudaFuncSetAttribute(gemm_h_kernel<128, 1, 3>,
                             cudaFuncAttributeMaxDynamicSharedMemorySize, SMEM_128_3);
        cudaFuncSetAttribute(gemm_h_kernel<256, 2, 4>,
                             cudaFuncAttributeMaxDynamicSharedMemorySize, SMEM_256_4);
        attr_done = true;
    }

    dim3 tb(32, 8);
    const long NELT = (long)MTOK * CDIM;
    const int F2H_GRID = (int)((NELT / 4 + 255) / 256);

    // ---- fork ----
    cudaEventRecord(evFork, 0);
    cudaStreamWaitEvent(s1, evFork, 0);

    // stream B (s1): query-side chain + weight preps for the back half
    f2h_kernel<<<F2H_GRID, 256, 0, s1>>>(query, p_query_h, NELT);
    concat_t_kernel<<<(128 * CDIM + 255) / 256, 256, 0, s1>>>(W_off, b_off, W_aw, b_aw);
    gemm_h_kernel<128, 0, 3><<<dim3(1, MTOK / BM), 256, SMEM_128_3, s1>>>(
        p_query_h, p_WcatT, p_bcat, p_offaw, NOFFAW, CDIM, 0,
        nullptr, nullptr, nullptr, nullptr, 0);
    cudaEventRecord(evB, s1);
    transpose_h_kernel<<<dim3(CDIM / 32, CDIM / 32), tb, 0, s1>>>(W_out, p_WoutT, CDIM, CDIM);
    transpose_h_kernel<<<dim3(DFF / 32,  CDIM / 32), tb, 0, s1>>>(W1, p_W1T, CDIM, DFF);
    transpose_h_kernel<<<dim3(CDIM / 32, DFF / 32),  tb, 0, s1>>>(W2, p_W2T, DFF, CDIM);
    cudaEventRecord(evC, s1);

    // stream A (default): src-side chain -> value
    f2h_kernel<<<F2H_GRID, 256>>>(src, p_src_h, NELT);
    transpose_h_kernel<<<dim3(CDIM / 32, CDIM / 32), tb>>>(W_val, p_WvalT, CDIM, CDIM);
    gemm_h_kernel<128, 1, 3><<<dim3(2, MTOK / BM), 256, SMEM_128_3>>>(
        p_src_h, p_WvalT, b_val, p_value_h, CDIM, CDIM, 0,
        nullptr, nullptr, nullptr, nullptr, 0);
    cudaEventRecord(evVal, 0);

    // ---- back half, pipelined in two row-chunks across the two streams ----
    const int MB0 = 313, MB1 = 312;            // 313+312 = 625 blocks of 128 rows
    const int ROW0 = 0,  ROW1 = MB0 * BM;      // chunk row offsets
    const int MBc[2]  = {MB0, MB1};
    const int ROWc[2] = {ROW0, ROW1};
    cudaStream_t st[2] = {(cudaStream_t)0, s1};

    // cross-stream joins: default needs offaw+weights (s1); s1 needs value (default)
    cudaStreamWaitEvent(0, evB, 0);
    cudaStreamWaitEvent(0, evC, 0);
    cudaStreamWaitEvent(s1, evVal, 0);

    for (int c = 0; c < 2; ++c) {
        cudaStream_t s = st[c];
        const int mb = MBc[c], row0 = ROWc[c];
        sample_kernel<<<mb * BM / 4, 256, 0, s>>>(refp, p_attn_h, row0);
        gemm_h_kernel<256, 2, 4><<<dim3(1, mb), 256, SMEM_256_4, s>>>(
            p_attn_h, p_WoutT, b_out, p_q2, CDIM, CDIM, 0,
            query, g1, be1, p_q2_h, row0);
        gemm_h_kernel<128, 1, 3><<<dim3(DFF / 128, mb), 256, SMEM_128_3, s>>>(
            p_q2_h, p_W1T, b1, p_ffn_h, DFF, CDIM, 1,
            nullptr, nullptr, nullptr, nullptr, row0);
        gemm_h_kernel<256, 2, 4><<<dim3(1, mb), 256, SMEM_256_4, s>>>(
            p_ffn_h, p_W2T, b2, out, CDIM, DFF, 0,
            p_q2, g2, be2, nullptr, row0);
    }

    // join s1 back to the origin stream (capture requires it)
    cudaEventRecord(evD, s1);
    cudaStreamWaitEvent(0, evD, 0);
}